// round 8
// baseline (speedup 1.0000x reference)
#include <cuda_runtime.h>
#include <cstdint>

#define NT 8192
#define DD 1024
#define UU 512
#define EE 8

// ---------------- helpers ----------------
__device__ __forceinline__ uint32_t f2tf32(float v) {
    uint32_t r; asm("cvt.rna.tf32.f32 %0, %1;" : "=r"(r) : "f"(v)); return r;
}
__device__ __forceinline__ void mma8(float* c, const uint32_t* a, const uint32_t* b) {
    asm volatile(
        "mma.sync.aligned.m16n8k8.row.col.f32.tf32.tf32.f32 "
        "{%0,%1,%2,%3}, {%4,%5,%6,%7}, {%8,%9}, {%0,%1,%2,%3};"
        : "+f"(c[0]), "+f"(c[1]), "+f"(c[2]), "+f"(c[3])
        : "r"(a[0]), "r"(a[1]), "r"(a[2]), "r"(a[3]), "r"(b[0]), "r"(b[1]));
}
// split one float4 into 4 (hi,lo) tf32 pairs and store as two float4
__device__ __forceinline__ void split_store4(float2* dst, float4 v) {
    uint32_t h0 = f2tf32(v.x), h1 = f2tf32(v.y), h2 = f2tf32(v.z), h3 = f2tf32(v.w);
    uint32_t l0 = f2tf32(v.x - __uint_as_float(h0));
    uint32_t l1 = f2tf32(v.y - __uint_as_float(h1));
    uint32_t l2 = f2tf32(v.z - __uint_as_float(h2));
    uint32_t l3 = f2tf32(v.w - __uint_as_float(h3));
    float4* d4 = (float4*)dst;
    d4[0] = make_float4(__uint_as_float(h0), __uint_as_float(l0),
                        __uint_as_float(h1), __uint_as_float(l1));
    d4[1] = make_float4(__uint_as_float(h2), __uint_as_float(l2),
                        __uint_as_float(h3), __uint_as_float(l3));
}

// ---------------- scratch ----------------
__device__ int   g_count[EE];
__device__ int   g_off[EE];
__device__ int   g_list[EE * NT];
__device__ float g_H[NT * UU];                 // 16 MB compact hidden

// ---------------- small kernels ----------------
__global__ void k_zero() { if (threadIdx.x < EE) g_count[threadIdx.x] = 0; }

__global__ void k_gate(const float* __restrict__ x,
                       const float* __restrict__ Wg,
                       const float* __restrict__ bg) {
    int warp = (blockIdx.x * blockDim.x + threadIdx.x) >> 5;
    int lane = threadIdx.x & 31;
    if (warp >= NT) return;
    const float* xr = x + (size_t)warp * DD;
    float acc[EE];
#pragma unroll
    for (int e = 0; e < EE; e++) acc[e] = 0.f;
    for (int d = lane; d < DD; d += 32) {
        float xv = xr[d];
        const float4* wr = (const float4*)(Wg + d * EE);
        float4 w0 = wr[0], w1 = wr[1];
        acc[0] += xv * w0.x; acc[1] += xv * w0.y;
        acc[2] += xv * w0.z; acc[3] += xv * w0.w;
        acc[4] += xv * w1.x; acc[5] += xv * w1.y;
        acc[6] += xv * w1.z; acc[7] += xv * w1.w;
    }
#pragma unroll
    for (int e = 0; e < EE; e++)
#pragma unroll
        for (int off = 16; off; off >>= 1)
            acc[e] += __shfl_xor_sync(0xffffffffu, acc[e], off);
    if (lane == 0) {
        int best = 0; float bv = acc[0] + bg[0];
#pragma unroll
        for (int e = 1; e < EE; e++) {
            float v = acc[e] + bg[e];
            if (v > bv) { bv = v; best = e; }
        }
        int pos = atomicAdd(&g_count[best], 1);
        g_list[best * NT + pos] = warp;
    }
}

__global__ void k_offs() {
    if (threadIdx.x == 0) {
        int s = 0;
#pragma unroll
        for (int e = 0; e < EE; e++) { g_off[e] = s; s += g_count[e]; }
    }
}

// ---------------- mma.sync tf32 GEMM with pre-split hi/lo SMEM ----------------
// CTA tile 128x64, 256 threads, 8 warps (4m x 2n), warp tile 32x32, BK=16.
// SMEM stores (hi,lo) tf32 pairs -> mainloop is LDS.64 + HMMA only.
// A stride 20 float2/row, B stride 68 float2/row (both ==4 mod 16 -> conflict-free).
#define A_STRIDE 20
#define B_STRIDE 68
#define A_STG (128 * A_STRIDE)       // float2 units per stage
#define B_STG (16 * B_STRIDE)
#define SMEM_DYN ((2 * A_STG + 2 * B_STG) * 8)   // 58368 bytes

template<int KK, bool FC2>
__global__ __launch_bounds__(256)
void k_gemm(const float* __restrict__ Asrc,
            const float* __restrict__ Bsrc,    // W1 / proj, [e][k][n] row stride UU
            const float* __restrict__ aux1,    // b1 (fc1) / ctrl (fc2)
            const float* __restrict__ aux2,    // unused  / scaling
            float* __restrict__ out)
{
    extern __shared__ char dyn[];
    float2* As = (float2*)dyn;                       // [2][128][A_STRIDE]
    float2* Bs = (float2*)(dyn + 2 * A_STG * 8);     // [2][16][B_STRIDE]
    __shared__ int   sRow[128];
    __shared__ float sBias[64];
    __shared__ float sCtrl[8][64];

    const int tid = threadIdx.x, wid = tid >> 5, lane = tid & 31;
    const int g = lane >> 2, tg = lane & 3;
    const int e = blockIdx.z;
    const int cnt = g_count[e];
    const int m0 = blockIdx.y * 128;
    if (m0 >= cnt) return;
    const int n0 = blockIdx.x * 64;
    const int base = g_off[e];

    if (tid < 128) {
        int m = m0 + tid;
        sRow[tid] = g_list[e * NT + (m < cnt ? m : cnt - 1)];
    }
    if (tid < 64)
        sBias[tid] = FC2 ? aux2[e * UU + n0 + tid] : aux1[e * UU + n0 + tid];
    if (FC2 && tid < 128) {
        int b = tid >> 4, c = (tid & 15) * 4;
        *(float4*)&sCtrl[b][c] =
            *(const float4*)(aux1 + (size_t)e * 8 * UU + (size_t)b * UU + n0 + c);
    }
    __syncthreads();

    // ---- copy assignments: A 2 float4/thread, B 1 float4/thread per chunk ----
    const int ra0 = tid >> 2, ca = (tid & 3) * 4;
    const float* gA0; const float* gA1;
    if (FC2) {
        int mA0 = m0 + ra0;      if (mA0 >= cnt) mA0 = cnt - 1;
        int mA1 = m0 + ra0 + 64; if (mA1 >= cnt) mA1 = cnt - 1;
        gA0 = g_H + (size_t)(base + mA0) * UU + ca;
        gA1 = g_H + (size_t)(base + mA1) * UU + ca;
    } else {
        gA0 = Asrc + (size_t)sRow[ra0] * DD + ca;
        gA1 = Asrc + (size_t)sRow[ra0 + 64] * DD + ca;
    }
    const int rb = tid >> 4, cb = (tid & 15) * 4;
    const float* gB = Bsrc + (size_t)e * UU * KK + (size_t)rb * UU + n0 + cb;

    float2* dA0b = As + ra0 * A_STRIDE + ca;
    float2* dA1b = As + (ra0 + 64) * A_STRIDE + ca;
    float2* dBb  = Bs + rb * B_STRIDE + cb;

    const int m_base = (wid >> 1) * 32;
    const int n_base = (wid & 1) * 32;

    float acc[2][4][4];
#pragma unroll
    for (int mi = 0; mi < 2; mi++)
#pragma unroll
        for (int ni = 0; ni < 4; ni++)
#pragma unroll
            for (int q = 0; q < 4; q++) acc[mi][ni][q] = 0.f;

    const int NCH = KK / 16;
    float4 pA0 = *(const float4*)gA0;
    float4 pA1 = *(const float4*)gA1;
    float4 pB  = *(const float4*)gB;

    for (int ch = 0; ch < NCH; ch++) {
        const int p = ch & 1;
        // convert + store current chunk
        split_store4(dA0b + p * A_STG, pA0);
        split_store4(dA1b + p * A_STG, pA1);
        split_store4(dBb  + p * B_STG, pB);
        // prefetch next chunk (LDG latency overlapped by sync+compute)
        if (ch + 1 < NCH) {
            const int k0 = (ch + 1) * 16;
            pA0 = *(const float4*)(gA0 + k0);
            pA1 = *(const float4*)(gA1 + k0);
            pB  = *(const float4*)(gB + (size_t)k0 * UU);
        }
        __syncthreads();
        const float2* Ap = As + p * A_STG;
        const float2* Bp = Bs + p * B_STG;
#pragma unroll
        for (int ks = 0; ks < 2; ks++) {
            const int k = ks * 8;
            uint32_t bh[4][2], bl[4][2];
#pragma unroll
            for (int ni = 0; ni < 4; ni++) {
                const int col = n_base + ni * 8 + g;
                float2 u0 = Bp[(k + tg) * B_STRIDE + col];
                float2 u1 = Bp[(k + tg + 4) * B_STRIDE + col];
                bh[ni][0] = __float_as_uint(u0.x); bl[ni][0] = __float_as_uint(u0.y);
                bh[ni][1] = __float_as_uint(u1.x); bl[ni][1] = __float_as_uint(u1.y);
            }
#pragma unroll
            for (int mi = 0; mi < 2; mi++) {
                const int r0 = m_base + mi * 16 + g;
                float2 v0 = Ap[r0 * A_STRIDE + k + tg];
                float2 v1 = Ap[(r0 + 8) * A_STRIDE + k + tg];
                float2 v2 = Ap[r0 * A_STRIDE + k + tg + 4];
                float2 v3 = Ap[(r0 + 8) * A_STRIDE + k + tg + 4];
                uint32_t ah[4], al[4];
                ah[0] = __float_as_uint(v0.x); al[0] = __float_as_uint(v0.y);
                ah[1] = __float_as_uint(v1.x); al[1] = __float_as_uint(v1.y);
                ah[2] = __float_as_uint(v2.x); al[2] = __float_as_uint(v2.y);
                ah[3] = __float_as_uint(v3.x); al[3] = __float_as_uint(v3.y);
#pragma unroll
                for (int ni = 0; ni < 4; ni++) {
                    mma8(acc[mi][ni], ah, bh[ni]);
                    mma8(acc[mi][ni], ah, bl[ni]);
                    mma8(acc[mi][ni], al, bh[ni]);
                }
            }
        }
        __syncthreads();
    }

    // ---------------- epilogue ----------------
#pragma unroll
    for (int mi = 0; mi < 2; mi++) {
#pragma unroll
        for (int half = 0; half < 2; half++) {
            const int rloc = m_base + mi * 16 + g + half * 8;
            const int m = m0 + rloc;
            if (m >= cnt) continue;
            float* dstRow;
            if (FC2) dstRow = out + (size_t)sRow[rloc] * UU + n0;
            else     dstRow = g_H + (size_t)(base + m) * UU + n0;
#pragma unroll
            for (int ni = 0; ni < 4; ni++) {
                const int cl = n_base + ni * 8 + 2 * tg;
                float z0 = acc[mi][ni][half * 2 + 0];
                float z1 = acc[mi][ni][half * 2 + 1];
                float2 v;
                if (!FC2) {
                    float t0 = z0 + sBias[cl], t1 = z1 + sBias[cl + 1];
                    v.x = t0 * __fdividef(1.f, 1.f + __expf(-t0));
                    v.y = t1 * __fdividef(1.f, 1.f + __expf(-t1));
                } else {
#pragma unroll
                    for (int q = 0; q < 2; q++) {
                        float z = q ? z1 : z0;
                        float xn = __fdividef(1.f, 1.f + __expf(-z));
                        float s = 1e-6f, num = 0.f;
#pragma unroll
                        for (int b = 0; b < 8; b++) {
                            float d = xn - (float)b * (1.0f / 7.0f);
                            float w = __expf(-32.f * d * d);
                            s += w;
                            num += w * sCtrl[b][cl + q];
                        }
                        float r = __fdividef(num, s) * sBias[cl + q];
                        if (q) v.y = r; else v.x = r;
                    }
                }
                *(float2*)(dstRow + cl) = v;
            }
        }
    }
}

// ---------------- launch ----------------
extern "C" void kernel_launch(void* const* d_in, const int* in_sizes, int n_in,
                              void* d_out, int out_size) {
    const float* x       = (const float*)d_in[0];
    const float* W1      = (const float*)d_in[1];
    const float* b1      = (const float*)d_in[2];
    const float* proj    = (const float*)d_in[3];
    const float* ctrl    = (const float*)d_in[4];
    const float* scaling = (const float*)d_in[5];
    const float* Wg      = (const float*)d_in[6];
    const float* bg      = (const float*)d_in[7];
    float* out = (float*)d_out;

    static int attr_done = 0;
    if (!attr_done) {
        cudaFuncSetAttribute(k_gemm<DD, false>,
                             cudaFuncAttributeMaxDynamicSharedMemorySize, SMEM_DYN);
        cudaFuncSetAttribute(k_gemm<UU, true>,
                             cudaFuncAttributeMaxDynamicSharedMemorySize, SMEM_DYN);
        attr_done = 1;
    }

    k_zero<<<1, 32>>>();
    k_gate<<<NT / 8, 256>>>(x, Wg, bg);
    k_offs<<<1, 1>>>();
    dim3 grid(UU / 64, NT / 128, EE);
    k_gemm<DD, false><<<grid, 256, SMEM_DYN>>>(x, W1, b1, nullptr, out);
    k_gemm<UU, true><<<grid, 256, SMEM_DYN>>>(nullptr, proj, ctrl, scaling, out);
}

// round 9
// speedup vs baseline: 1.7929x; 1.7929x over previous
#include <cuda_runtime.h>
#include <cstdint>

#define NT 8192
#define DD 1024
#define UU 512
#define EE 8

// ---------------- helpers ----------------
__device__ __forceinline__ uint32_t packbf(float lo, float hi) {
    uint32_t r;  // first src operand -> upper half
    asm("cvt.rn.bf16x2.f32 %0, %1, %2;" : "=r"(r) : "f"(hi), "f"(lo));
    return r;
}
__device__ __forceinline__ void mma16(float* c, const uint32_t* a, const uint32_t* b) {
    asm volatile(
        "mma.sync.aligned.m16n8k16.row.col.f32.bf16.bf16.f32 "
        "{%0,%1,%2,%3}, {%4,%5,%6,%7}, {%8,%9}, {%0,%1,%2,%3};"
        : "+f"(c[0]), "+f"(c[1]), "+f"(c[2]), "+f"(c[3])
        : "r"(a[0]), "r"(a[1]), "r"(a[2]), "r"(a[3]), "r"(b[0]), "r"(b[1]));
}
// split float4 -> hi/lo bf16x2 pairs, store 8B to each plane
__device__ __forceinline__ void split_store(uint16_t* hp, uint16_t* lp, float4 v) {
    uint32_t h01 = packbf(v.x, v.y);
    uint32_t h23 = packbf(v.z, v.w);
    float r0 = v.x - __uint_as_float(h01 << 16);
    float r1 = v.y - __uint_as_float(h01 & 0xffff0000u);
    float r2 = v.z - __uint_as_float(h23 << 16);
    float r3 = v.w - __uint_as_float(h23 & 0xffff0000u);
    uint32_t l01 = packbf(r0, r1);
    uint32_t l23 = packbf(r2, r3);
    *(uint2*)hp = make_uint2(h01, h23);
    *(uint2*)lp = make_uint2(l01, l23);
}

// ---------------- scratch ----------------
__device__ int   g_count[EE];
__device__ int   g_off[EE];
__device__ int   g_list[EE * NT];
__device__ float g_H[NT * UU];

// ---------------- small kernels ----------------
__global__ void k_zero() { if (threadIdx.x < EE) g_count[threadIdx.x] = 0; }

__global__ void k_gate(const float* __restrict__ x,
                       const float* __restrict__ Wg,
                       const float* __restrict__ bg) {
    int warp = (blockIdx.x * blockDim.x + threadIdx.x) >> 5;
    int lane = threadIdx.x & 31;
    if (warp >= NT) return;
    const float* xr = x + (size_t)warp * DD;
    float acc[EE];
#pragma unroll
    for (int e = 0; e < EE; e++) acc[e] = 0.f;
    for (int d = lane; d < DD; d += 32) {
        float xv = xr[d];
        const float4* wr = (const float4*)(Wg + d * EE);
        float4 w0 = wr[0], w1 = wr[1];
        acc[0] += xv * w0.x; acc[1] += xv * w0.y;
        acc[2] += xv * w0.z; acc[3] += xv * w0.w;
        acc[4] += xv * w1.x; acc[5] += xv * w1.y;
        acc[6] += xv * w1.z; acc[7] += xv * w1.w;
    }
#pragma unroll
    for (int e = 0; e < EE; e++)
#pragma unroll
        for (int off = 16; off; off >>= 1)
            acc[e] += __shfl_xor_sync(0xffffffffu, acc[e], off);
    if (lane == 0) {
        int best = 0; float bv = acc[0] + bg[0];
#pragma unroll
        for (int e = 1; e < EE; e++) {
            float v = acc[e] + bg[e];
            if (v > bv) { bv = v; best = e; }
        }
        int pos = atomicAdd(&g_count[best], 1);
        g_list[best * NT + pos] = warp;
    }
}

__global__ void k_offs() {
    if (threadIdx.x == 0) {
        int s = 0;
#pragma unroll
        for (int e = 0; e < EE; e++) { g_off[e] = s; s += g_count[e]; }
    }
}

// ---------------- bf16 m16n8k16 GEMM, 3xBF16 split ----------------
// CTA 128x64, 256 threads, 8 warps (4m x 2n), warp tile 32x32, BK=32.
// SMEM planes (bf16, row stride 40): Ah/Al [128][40], Bh/Bl [64][40] ([n][k]).
#define BKC 32
#define PSTR 40
#define AH_OFF 0
#define AL_OFF (128 * PSTR)
#define BH_OFF (2 * 128 * PSTR)
#define BL_OFF (2 * 128 * PSTR + 64 * PSTR)
#define STG_ELEM (2 * 128 * PSTR + 2 * 64 * PSTR)     // 15360 bf16
#define SMEM_DYN (2 * STG_ELEM * 2)                   // 61440 bytes

template<int KK, bool FC2>
__global__ __launch_bounds__(256)
void k_gemm(const float* __restrict__ Asrc,
            const float* __restrict__ Bsrc,    // [e][k][n], row stride UU
            const float* __restrict__ aux1,    // b1 / ctrl
            const float* __restrict__ aux2,    // -- / scaling
            float* __restrict__ out)
{
    extern __shared__ uint16_t pl[];
    __shared__ int   sRow[128];
    __shared__ float sBias[64];
    __shared__ float sCtrl[8][64];

    const int tid = threadIdx.x, wid = tid >> 5, lane = tid & 31;
    const int g = lane >> 2, tg = lane & 3;
    const int e = blockIdx.z;
    const int cnt = g_count[e];
    const int m0 = blockIdx.y * 128;
    if (m0 >= cnt) return;
    const int n0 = blockIdx.x * 64;
    const int base = g_off[e];

    if (tid < 128) {
        int m = m0 + tid;
        sRow[tid] = g_list[e * NT + (m < cnt ? m : cnt - 1)];
    }
    if (tid < 64)
        sBias[tid] = FC2 ? aux2[e * UU + n0 + tid] : aux1[e * UU + n0 + tid];
    if (FC2 && tid < 128) {
        int b = tid >> 4, c = (tid & 15) * 4;
        *(float4*)&sCtrl[b][c] =
            *(const float4*)(aux1 + (size_t)e * 8 * UU + (size_t)b * UU + n0 + c);
    }
    __syncthreads();

    // ---- staging assignments ----
    // A: thread -> row = tid>>1 (0..127), khalf = (tid&1)*16; 4 float4 per chunk
    const int rowA = tid >> 1, k0A = (tid & 1) * 16;
    const float* gA;
    if (FC2) {
        int mA = m0 + rowA; if (mA >= cnt) mA = cnt - 1;
        gA = g_H + (size_t)(base + mA) * UU + k0A;
    } else {
        gA = Asrc + (size_t)sRow[rowA] * DD + k0A;
    }
    uint16_t* dAh = pl + AH_OFF + rowA * PSTR + k0A;
    uint16_t* dAl = pl + AL_OFF + rowA * PSTR + k0A;
    // B: thread -> n = tid&63, k0b = (tid>>6)*8; 8 strided LDG.32 per chunk
    const int nB = tid & 63, k0B = (tid >> 6) * 8;
    const float* gB = Bsrc + (size_t)e * UU * KK + (size_t)k0B * UU + n0 + nB;
    uint16_t* dBh = pl + BH_OFF + nB * PSTR + k0B;
    uint16_t* dBl = pl + BL_OFF + nB * PSTR + k0B;

    const int m_base = (wid >> 1) * 32;
    const int n_base = (wid & 1) * 32;

    float acc[2][4][4];
#pragma unroll
    for (int mi = 0; mi < 2; mi++)
#pragma unroll
        for (int ni = 0; ni < 4; ni++)
#pragma unroll
            for (int q = 0; q < 4; q++) acc[mi][ni][q] = 0.f;

    const int NCH = KK / BKC;
    // prefetch chunk 0
    float4 pA[4]; float pB[8];
#pragma unroll
    for (int j = 0; j < 4; j++) pA[j] = *(const float4*)(gA + 4 * j);
#pragma unroll
    for (int j = 0; j < 8; j++) pB[j] = gB[(size_t)j * UU];

    for (int ch = 0; ch < NCH; ch++) {
        const uint32_t so = (uint32_t)(ch & 1) * STG_ELEM;
        // convert + store current chunk
#pragma unroll
        for (int j = 0; j < 4; j++)
            split_store(dAh + so + 4 * j, dAl + so + 4 * j, pA[j]);
        split_store(dBh + so,     dBl + so,     make_float4(pB[0], pB[1], pB[2], pB[3]));
        split_store(dBh + so + 4, dBl + so + 4, make_float4(pB[4], pB[5], pB[6], pB[7]));
        // prefetch next chunk (overlaps barrier + MMA below)
        if (ch + 1 < NCH) {
            const int k0 = (ch + 1) * BKC;
#pragma unroll
            for (int j = 0; j < 4; j++) pA[j] = *(const float4*)(gA + k0 + 4 * j);
            const float* gBn = gB + (size_t)k0 * UU;
#pragma unroll
            for (int j = 0; j < 8; j++) pB[j] = gBn[(size_t)j * UU];
        }
        __syncthreads();
        const uint16_t* Ah = pl + AH_OFF + so;
        const uint16_t* Al = pl + AL_OFF + so;
        const uint16_t* Bh = pl + BH_OFF + so;
        const uint16_t* Bl = pl + BL_OFF + so;
#pragma unroll
        for (int ks = 0; ks < 2; ks++) {
            const int kb = ks * 16 + 2 * tg;
            uint32_t bh[4][2], bl[4][2];
#pragma unroll
            for (int ni = 0; ni < 4; ni++) {
                const int nr = (n_base + ni * 8 + g) * PSTR + kb;
                bh[ni][0] = *(const uint32_t*)(Bh + nr);
                bh[ni][1] = *(const uint32_t*)(Bh + nr + 8);
                bl[ni][0] = *(const uint32_t*)(Bl + nr);
                bl[ni][1] = *(const uint32_t*)(Bl + nr + 8);
            }
#pragma unroll
            for (int mi = 0; mi < 2; mi++) {
                const int r0 = (m_base + mi * 16 + g) * PSTR + kb;
                const int r8 = r0 + 8 * PSTR;
                uint32_t ah[4], al[4];
                ah[0] = *(const uint32_t*)(Ah + r0);
                ah[1] = *(const uint32_t*)(Ah + r8);
                ah[2] = *(const uint32_t*)(Ah + r0 + 8);
                ah[3] = *(const uint32_t*)(Ah + r8 + 8);
                al[0] = *(const uint32_t*)(Al + r0);
                al[1] = *(const uint32_t*)(Al + r8);
                al[2] = *(const uint32_t*)(Al + r0 + 8);
                al[3] = *(const uint32_t*)(Al + r8 + 8);
#pragma unroll
                for (int ni = 0; ni < 4; ni++) {
                    mma16(acc[mi][ni], ah, bh[ni]);
                    mma16(acc[mi][ni], ah, bl[ni]);
                    mma16(acc[mi][ni], al, bh[ni]);
                }
            }
        }
        __syncthreads();
    }

    // ---------------- epilogue ----------------
#pragma unroll
    for (int mi = 0; mi < 2; mi++) {
#pragma unroll
        for (int half = 0; half < 2; half++) {
            const int rloc = m_base + mi * 16 + g + half * 8;
            const int m = m0 + rloc;
            if (m >= cnt) continue;
            float* dstRow;
            if (FC2) dstRow = out + (size_t)sRow[rloc] * UU + n0;
            else     dstRow = g_H + (size_t)(base + m) * UU + n0;
#pragma unroll
            for (int ni = 0; ni < 4; ni++) {
                const int cl = n_base + ni * 8 + 2 * tg;
                float z0 = acc[mi][ni][half * 2 + 0];
                float z1 = acc[mi][ni][half * 2 + 1];
                float2 v;
                if (!FC2) {
                    float t0 = z0 + sBias[cl], t1 = z1 + sBias[cl + 1];
                    v.x = t0 * __fdividef(1.f, 1.f + __expf(-t0));
                    v.y = t1 * __fdividef(1.f, 1.f + __expf(-t1));
                } else {
#pragma unroll
                    for (int q = 0; q < 2; q++) {
                        float z = q ? z1 : z0;
                        float xn = __fdividef(1.f, 1.f + __expf(-z));
                        float s = 1e-6f, num = 0.f;
#pragma unroll
                        for (int b = 0; b < 8; b++) {
                            float d = xn - (float)b * (1.0f / 7.0f);
                            float w = __expf(-32.f * d * d);
                            s += w;
                            num += w * sCtrl[b][cl + q];
                        }
                        float r = __fdividef(num, s) * sBias[cl + q];
                        if (q) v.y = r; else v.x = r;
                    }
                }
                *(float2*)(dstRow + cl) = v;
            }
        }
    }
}

// ---------------- launch ----------------
extern "C" void kernel_launch(void* const* d_in, const int* in_sizes, int n_in,
                              void* d_out, int out_size) {
    const float* x       = (const float*)d_in[0];
    const float* W1      = (const float*)d_in[1];
    const float* b1      = (const float*)d_in[2];
    const float* proj    = (const float*)d_in[3];
    const float* ctrl    = (const float*)d_in[4];
    const float* scaling = (const float*)d_in[5];
    const float* Wg      = (const float*)d_in[6];
    const float* bg      = (const float*)d_in[7];
    float* out = (float*)d_out;

    static int attr_done = 0;
    if (!attr_done) {
        cudaFuncSetAttribute(k_gemm<DD, false>,
                             cudaFuncAttributeMaxDynamicSharedMemorySize, SMEM_DYN);
        cudaFuncSetAttribute(k_gemm<UU, true>,
                             cudaFuncAttributeMaxDynamicSharedMemorySize, SMEM_DYN);
        attr_done = 1;
    }

    k_zero<<<1, 32>>>();
    k_gate<<<NT / 8, 256>>>(x, Wg, bg);
    k_offs<<<1, 1>>>();
    dim3 grid(UU / 64, NT / 128, EE);
    k_gemm<DD, false><<<grid, 256, SMEM_DYN>>>(x, W1, b1, nullptr, out);
    k_gemm<UU, true><<<grid, 256, SMEM_DYN>>>(nullptr, proj, ctrl, scaling, out);
}

// round 10
// speedup vs baseline: 1.9408x; 1.0825x over previous
#include <cuda_runtime.h>
#include <cstdint>

#define NT 8192
#define DD 1024
#define UU 512
#define EE 8

// ---------------- helpers ----------------
__device__ __forceinline__ uint32_t smem_to_u32(const void* p) {
    uint32_t a;
    asm("{ .reg .u64 t; cvta.to.shared.u64 t, %1; cvt.u32.u64 %0, t; }" : "=r"(a) : "l"(p));
    return a;
}
__device__ __forceinline__ uint32_t packbf(float lo, float hi) {
    uint32_t r;  // first src operand -> upper half
    asm("cvt.rn.bf16x2.f32 %0, %1, %2;" : "=r"(r) : "f"(hi), "f"(lo));
    return r;
}
__device__ __forceinline__ void mma16(float* c, const uint32_t* a, const uint32_t* b) {
    asm volatile(
        "mma.sync.aligned.m16n8k16.row.col.f32.bf16.bf16.f32 "
        "{%0,%1,%2,%3}, {%4,%5,%6,%7}, {%8,%9}, {%0,%1,%2,%3};"
        : "+f"(c[0]), "+f"(c[1]), "+f"(c[2]), "+f"(c[3])
        : "r"(a[0]), "r"(a[1]), "r"(a[2]), "r"(a[3]), "r"(b[0]), "r"(b[1]));
}
#define LDSM4(r, addr) \
    asm volatile("ldmatrix.sync.aligned.m8n8.x4.shared.b16 {%0,%1,%2,%3}, [%4];" \
        : "=r"((r)[0]), "=r"((r)[1]), "=r"((r)[2]), "=r"((r)[3]) : "r"(addr))

// split float4 -> hi/lo bf16x2 pairs, store 8B to each plane
__device__ __forceinline__ void split_store(uint16_t* hp, uint16_t* lp, float4 v) {
    uint32_t h01 = packbf(v.x, v.y);
    uint32_t h23 = packbf(v.z, v.w);
    float r0 = v.x - __uint_as_float(h01 << 16);
    float r1 = v.y - __uint_as_float(h01 & 0xffff0000u);
    float r2 = v.z - __uint_as_float(h23 << 16);
    float r3 = v.w - __uint_as_float(h23 & 0xffff0000u);
    uint32_t l01 = packbf(r0, r1);
    uint32_t l23 = packbf(r2, r3);
    *(uint2*)hp = make_uint2(h01, h23);
    *(uint2*)lp = make_uint2(l01, l23);
}

// ---------------- scratch ----------------
__device__ int   g_count[EE];
__device__ int   g_off[EE];
__device__ int   g_list[EE * NT];
__device__ float g_H[NT * UU];

// ---------------- small kernels ----------------
__global__ void k_zero() { if (threadIdx.x < EE) g_count[threadIdx.x] = 0; }

__global__ void k_gate(const float* __restrict__ x,
                       const float* __restrict__ Wg,
                       const float* __restrict__ bg) {
    int warp = (blockIdx.x * blockDim.x + threadIdx.x) >> 5;
    int lane = threadIdx.x & 31;
    if (warp >= NT) return;
    const float* xr = x + (size_t)warp * DD;
    float acc[EE];
#pragma unroll
    for (int e = 0; e < EE; e++) acc[e] = 0.f;
    for (int d = lane; d < DD; d += 32) {
        float xv = xr[d];
        const float4* wr = (const float4*)(Wg + d * EE);
        float4 w0 = wr[0], w1 = wr[1];
        acc[0] += xv * w0.x; acc[1] += xv * w0.y;
        acc[2] += xv * w0.z; acc[3] += xv * w0.w;
        acc[4] += xv * w1.x; acc[5] += xv * w1.y;
        acc[6] += xv * w1.z; acc[7] += xv * w1.w;
    }
#pragma unroll
    for (int e = 0; e < EE; e++)
#pragma unroll
        for (int off = 16; off; off >>= 1)
            acc[e] += __shfl_xor_sync(0xffffffffu, acc[e], off);
    if (lane == 0) {
        int best = 0; float bv = acc[0] + bg[0];
#pragma unroll
        for (int e = 1; e < EE; e++) {
            float v = acc[e] + bg[e];
            if (v > bv) { bv = v; best = e; }
        }
        int pos = atomicAdd(&g_count[best], 1);
        g_list[best * NT + pos] = warp;
    }
}

__global__ void k_offs() {
    if (threadIdx.x == 0) {
        int s = 0;
#pragma unroll
        for (int e = 0; e < EE; e++) { g_off[e] = s; s += g_count[e]; }
    }
}

// ---------------- bf16 m16n8k16 GEMM, 3xBF16 split, ldmatrix fragments ----------------
// CTA 128x64, 256 threads, 8 warps (4m x 2n), warp tile 32x32, BK=32.
// SMEM planes (bf16, row stride 40): Ah/Al [128][40], Bh/Bl [64][40] ([n][k]).
// Stride 40 elem = 80 B -> ldmatrix's 8 rows hit banks {0,20,8,28,16,4,24,12}*4B,
// covering all 32 banks exactly once: conflict-free.
#define BKC 32
#define PSTR 40
#define AH_OFF 0
#define AL_OFF (128 * PSTR)
#define BH_OFF (2 * 128 * PSTR)
#define BL_OFF (2 * 128 * PSTR + 64 * PSTR)
#define STG_ELEM (2 * 128 * PSTR + 2 * 64 * PSTR)     // 15360 bf16
#define SMEM_DYN (2 * STG_ELEM * 2)                   // 61440 bytes

template<int KK, bool FC2>
__global__ __launch_bounds__(256)
void k_gemm(const float* __restrict__ Asrc,
            const float* __restrict__ Bsrc,    // [e][k][n], row stride UU
            const float* __restrict__ aux1,    // b1 / ctrl
            const float* __restrict__ aux2,    // -- / scaling
            float* __restrict__ out)
{
    extern __shared__ uint16_t pl[];
    __shared__ int   sRow[128];
    __shared__ float sBias[64];
    __shared__ float sCtrl[8][64];

    const int tid = threadIdx.x, wid = tid >> 5, lane = tid & 31;
    const int g = lane >> 2, tg = lane & 3;
    const int e = blockIdx.z;
    const int cnt = g_count[e];
    const int m0 = blockIdx.y * 128;
    if (m0 >= cnt) return;
    const int n0 = blockIdx.x * 64;
    const int base = g_off[e];

    if (tid < 128) {
        int m = m0 + tid;
        sRow[tid] = g_list[e * NT + (m < cnt ? m : cnt - 1)];
    }
    if (tid < 64)
        sBias[tid] = FC2 ? aux2[e * UU + n0 + tid] : aux1[e * UU + n0 + tid];
    if (FC2 && tid < 128) {
        int b = tid >> 4, c = (tid & 15) * 4;
        *(float4*)&sCtrl[b][c] =
            *(const float4*)(aux1 + (size_t)e * 8 * UU + (size_t)b * UU + n0 + c);
    }
    __syncthreads();

    // ---- staging assignments ----
    const int rowA = tid >> 1, k0A = (tid & 1) * 16;
    const float* gA;
    if (FC2) {
        int mA = m0 + rowA; if (mA >= cnt) mA = cnt - 1;
        gA = g_H + (size_t)(base + mA) * UU + k0A;
    } else {
        gA = Asrc + (size_t)sRow[rowA] * DD + k0A;
    }
    uint16_t* dAh = pl + AH_OFF + rowA * PSTR + k0A;
    uint16_t* dAl = pl + AL_OFF + rowA * PSTR + k0A;
    const int nB = tid & 63, k0B = (tid >> 6) * 8;
    const float* gB = Bsrc + (size_t)e * UU * KK + (size_t)k0B * UU + n0 + nB;
    uint16_t* dBh = pl + BH_OFF + nB * PSTR + k0B;
    uint16_t* dBl = pl + BL_OFF + nB * PSTR + k0B;

    const int m_base = (wid >> 1) * 32;
    const int n_base = (wid & 1) * 32;

    // ---- ldmatrix lane addresses (byte addrs into shared) ----
    const uint32_t plU = smem_to_u32(pl);
    const uint32_t aRow = (uint32_t)(m_base + (lane & 7) + ((lane >> 3) & 1) * 8);
    const uint32_t aCol = (uint32_t)(((lane >> 4) & 1) * 8);
    const uint32_t aH = plU + (AH_OFF + aRow * PSTR + aCol) * 2;
    const uint32_t aL = plU + (AL_OFF + aRow * PSTR + aCol) * 2;
    const uint32_t bRow = (uint32_t)(n_base + (lane & 7) + ((lane >> 4) & 1) * 8);
    const uint32_t bCol = (uint32_t)(((lane >> 3) & 1) * 8);
    const uint32_t bH = plU + (BH_OFF + bRow * PSTR + bCol) * 2;
    const uint32_t bL = plU + (BL_OFF + bRow * PSTR + bCol) * 2;

    float acc[2][4][4];
#pragma unroll
    for (int mi = 0; mi < 2; mi++)
#pragma unroll
        for (int ni = 0; ni < 4; ni++)
#pragma unroll
            for (int q = 0; q < 4; q++) acc[mi][ni][q] = 0.f;

    const int NCH = KK / BKC;
    float4 pA[4]; float pB[8];
#pragma unroll
    for (int j = 0; j < 4; j++) pA[j] = *(const float4*)(gA + 4 * j);
#pragma unroll
    for (int j = 0; j < 8; j++) pB[j] = gB[(size_t)j * UU];

    for (int ch = 0; ch < NCH; ch++) {
        const uint32_t so = (uint32_t)(ch & 1) * STG_ELEM;
        const uint32_t so2 = so * 2;
        // convert + store current chunk
#pragma unroll
        for (int j = 0; j < 4; j++)
            split_store(dAh + so + 4 * j, dAl + so + 4 * j, pA[j]);
        split_store(dBh + so,     dBl + so,     make_float4(pB[0], pB[1], pB[2], pB[3]));
        split_store(dBh + so + 4, dBl + so + 4, make_float4(pB[4], pB[5], pB[6], pB[7]));
        // prefetch next chunk
        if (ch + 1 < NCH) {
            const int k0 = (ch + 1) * BKC;
#pragma unroll
            for (int j = 0; j < 4; j++) pA[j] = *(const float4*)(gA + k0 + 4 * j);
            const float* gBn = gB + (size_t)k0 * UU;
#pragma unroll
            for (int j = 0; j < 8; j++) pB[j] = gBn[(size_t)j * UU];
        }
        __syncthreads();
#pragma unroll
        for (int ks = 0; ks < 2; ks++) {
            const uint32_t kso = so2 + (uint32_t)ks * 32;   // 16 bf16 = 32 bytes
            uint32_t bh0[4], bh1[4], bl0[4], bl1[4];
            LDSM4(bh0, bH + kso);
            LDSM4(bh1, bH + kso + 16 * PSTR * 2);
            LDSM4(bl0, bL + kso);
            LDSM4(bl1, bL + kso + 16 * PSTR * 2);
#pragma unroll
            for (int mi = 0; mi < 2; mi++) {
                const uint32_t moff = (uint32_t)mi * (16 * PSTR * 2);
                uint32_t ah[4], al[4];
                LDSM4(ah, aH + kso + moff);
                LDSM4(al, aL + kso + moff);
                mma16(acc[mi][0], ah, bh0);
                mma16(acc[mi][0], ah, bl0);
                mma16(acc[mi][0], al, bh0);
                mma16(acc[mi][1], ah, bh0 + 2);
                mma16(acc[mi][1], ah, bl0 + 2);
                mma16(acc[mi][1], al, bh0 + 2);
                mma16(acc[mi][2], ah, bh1);
                mma16(acc[mi][2], ah, bl1);
                mma16(acc[mi][2], al, bh1);
                mma16(acc[mi][3], ah, bh1 + 2);
                mma16(acc[mi][3], ah, bl1 + 2);
                mma16(acc[mi][3], al, bh1 + 2);
            }
        }
        __syncthreads();
    }

    // ---------------- epilogue ----------------
#pragma unroll
    for (int mi = 0; mi < 2; mi++) {
#pragma unroll
        for (int half = 0; half < 2; half++) {
            const int rloc = m_base + mi * 16 + g + half * 8;
            const int m = m0 + rloc;
            if (m >= cnt) continue;
            float* dstRow;
            if (FC2) dstRow = out + (size_t)sRow[rloc] * UU + n0;
            else     dstRow = g_H + (size_t)(base + m) * UU + n0;
#pragma unroll
            for (int ni = 0; ni < 4; ni++) {
                const int cl = n_base + ni * 8 + 2 * tg;
                float z0 = acc[mi][ni][half * 2 + 0];
                float z1 = acc[mi][ni][half * 2 + 1];
                float2 v;
                if (!FC2) {
                    float t0 = z0 + sBias[cl], t1 = z1 + sBias[cl + 1];
                    v.x = t0 * __fdividef(1.f, 1.f + __expf(-t0));
                    v.y = t1 * __fdividef(1.f, 1.f + __expf(-t1));
                } else {
#pragma unroll
                    for (int q = 0; q < 2; q++) {
                        float z = q ? z1 : z0;
                        float xn = __fdividef(1.f, 1.f + __expf(-z));
                        float s = 1e-6f, num = 0.f;
#pragma unroll
                        for (int b = 0; b < 8; b++) {
                            float d = xn - (float)b * (1.0f / 7.0f);
                            float w = __expf(-32.f * d * d);
                            s += w;
                            num += w * sCtrl[b][cl + q];
                        }
                        float r = __fdividef(num, s) * sBias[cl + q];
                        if (q) v.y = r; else v.x = r;
                    }
                }
                *(float2*)(dstRow + cl) = v;
            }
        }
    }
}

// ---------------- launch ----------------
extern "C" void kernel_launch(void* const* d_in, const int* in_sizes, int n_in,
                              void* d_out, int out_size) {
    const float* x       = (const float*)d_in[0];
    const float* W1      = (const float*)d_in[1];
    const float* b1      = (const float*)d_in[2];
    const float* proj    = (const float*)d_in[3];
    const float* ctrl    = (const float*)d_in[4];
    const float* scaling = (const float*)d_in[5];
    const float* Wg      = (const float*)d_in[6];
    const float* bg      = (const float*)d_in[7];
    float* out = (float*)d_out;

    static int attr_done = 0;
    if (!attr_done) {
        cudaFuncSetAttribute(k_gemm<DD, false>,
                             cudaFuncAttributeMaxDynamicSharedMemorySize, SMEM_DYN);
        cudaFuncSetAttribute(k_gemm<UU, true>,
                             cudaFuncAttributeMaxDynamicSharedMemorySize, SMEM_DYN);
        attr_done = 1;
    }

    k_zero<<<1, 32>>>();
    k_gate<<<NT / 8, 256>>>(x, Wg, bg);
    k_offs<<<1, 1>>>();
    dim3 grid(UU / 64, NT / 128, EE);
    k_gemm<DD, false><<<grid, 256, SMEM_DYN>>>(x, W1, b1, nullptr, out);
    k_gemm<UU, true><<<grid, 256, SMEM_DYN>>>(nullptr, proj, ctrl, scaling, out);
}

// round 11
// speedup vs baseline: 2.0111x; 1.0362x over previous
#include <cuda_runtime.h>
#include <cstdint>

#define NT 8192
#define DD 1024
#define UU 512
#define EE 8

// ---------------- helpers ----------------
__device__ __forceinline__ uint32_t smem_to_u32(const void* p) {
    uint32_t a;
    asm("{ .reg .u64 t; cvta.to.shared.u64 t, %1; cvt.u32.u64 %0, t; }" : "=r"(a) : "l"(p));
    return a;
}
__device__ __forceinline__ uint32_t packbf(float lo, float hi) {
    uint32_t r;  // first src operand -> upper half
    asm("cvt.rn.bf16x2.f32 %0, %1, %2;" : "=r"(r) : "f"(hi), "f"(lo));
    return r;
}
__device__ __forceinline__ uint32_t prmt(uint32_t a, uint32_t b, uint32_t s) {
    uint32_t d; asm("prmt.b32 %0,%1,%2,%3;" : "=r"(d) : "r"(a), "r"(b), "r"(s));
    return d;
}
// pack float -> (bf16 hi << 16) | bf16 lo-residual
__device__ __forceinline__ uint32_t packsplit(float v) {
    uint16_t h; asm("cvt.rn.bf16.f32 %0, %1;" : "=h"(h) : "f"(v));
    float hf = __uint_as_float(((uint32_t)h) << 16);
    uint16_t l; float r = v - hf;
    asm("cvt.rn.bf16.f32 %0, %1;" : "=h"(l) : "f"(r));
    return (((uint32_t)h) << 16) | (uint32_t)l;
}
__device__ __forceinline__ void mma16(float* c, const uint32_t* a, const uint32_t* b) {
    asm volatile(
        "mma.sync.aligned.m16n8k16.row.col.f32.bf16.bf16.f32 "
        "{%0,%1,%2,%3}, {%4,%5,%6,%7}, {%8,%9}, {%0,%1,%2,%3};"
        : "+f"(c[0]), "+f"(c[1]), "+f"(c[2]), "+f"(c[3])
        : "r"(a[0]), "r"(a[1]), "r"(a[2]), "r"(a[3]), "r"(b[0]), "r"(b[1]));
}
#define LDSM4(r, addr) \
    asm volatile("ldmatrix.sync.aligned.m8n8.x4.shared.b16 {%0,%1,%2,%3}, [%4];" \
        : "=r"((r)[0]), "=r"((r)[1]), "=r"((r)[2]), "=r"((r)[3]) : "r"(addr))

// split float4 -> hi/lo bf16x2 pairs, store 8B to each plane
__device__ __forceinline__ void split_store(uint16_t* hp, uint16_t* lp, float4 v) {
    uint32_t h01 = packbf(v.x, v.y);
    uint32_t h23 = packbf(v.z, v.w);
    float r0 = v.x - __uint_as_float(h01 << 16);
    float r1 = v.y - __uint_as_float(h01 & 0xffff0000u);
    float r2 = v.z - __uint_as_float(h23 << 16);
    float r3 = v.w - __uint_as_float(h23 & 0xffff0000u);
    uint32_t l01 = packbf(r0, r1);
    uint32_t l23 = packbf(r2, r3);
    *(uint2*)hp = make_uint2(h01, h23);
    *(uint2*)lp = make_uint2(l01, l23);
}

// ---------------- scratch ----------------
__device__ int      g_count[EE];
__device__ int      g_off[EE];
__device__ int      g_list[EE * NT];
__device__ uint32_t g_Hp[NT * UU];     // 16 MB packed (bf16 hi<<16 | bf16 lo)

// ---------------- small kernels ----------------
__global__ void k_zero() { if (threadIdx.x < EE) g_count[threadIdx.x] = 0; }

__global__ void k_gate(const float* __restrict__ x,
                       const float* __restrict__ Wg,
                       const float* __restrict__ bg) {
    int warp = (blockIdx.x * blockDim.x + threadIdx.x) >> 5;
    int lane = threadIdx.x & 31;
    if (warp >= NT) return;
    const float* xr = x + (size_t)warp * DD;
    float acc[EE];
#pragma unroll
    for (int e = 0; e < EE; e++) acc[e] = 0.f;
    for (int d = lane; d < DD; d += 32) {
        float xv = xr[d];
        const float4* wr = (const float4*)(Wg + d * EE);
        float4 w0 = wr[0], w1 = wr[1];
        acc[0] += xv * w0.x; acc[1] += xv * w0.y;
        acc[2] += xv * w0.z; acc[3] += xv * w0.w;
        acc[4] += xv * w1.x; acc[5] += xv * w1.y;
        acc[6] += xv * w1.z; acc[7] += xv * w1.w;
    }
#pragma unroll
    for (int e = 0; e < EE; e++)
#pragma unroll
        for (int off = 16; off; off >>= 1)
            acc[e] += __shfl_xor_sync(0xffffffffu, acc[e], off);
    if (lane == 0) {
        int best = 0; float bv = acc[0] + bg[0];
#pragma unroll
        for (int e = 1; e < EE; e++) {
            float v = acc[e] + bg[e];
            if (v > bv) { bv = v; best = e; }
        }
        int pos = atomicAdd(&g_count[best], 1);
        g_list[best * NT + pos] = warp;
    }
}

__global__ void k_offs() {
    if (threadIdx.x == 0) {
        int s = 0;
#pragma unroll
        for (int e = 0; e < EE; e++) { g_off[e] = s; s += g_count[e]; }
    }
}

// ---------------- bf16 m16n8k16 GEMM, 3xBF16 split, ldmatrix fragments ----------------
// CTA 128x128, 256 threads, 8 warps (2m x 4n), warp tile 64x32, BK=32.
// SMEM planes (bf16, row stride 40): Ah/Al [128][40], Bh/Bl [128][40] ([n][k]).
#define BKC 32
#define PSTR 40
#define AH_OFF 0
#define AL_OFF (128 * PSTR)
#define BH_OFF (2 * 128 * PSTR)
#define BL_OFF (3 * 128 * PSTR)
#define STG_ELEM (4 * 128 * PSTR)                  // 20480 bf16
#define SMEM_DYN (2 * STG_ELEM * 2)                // 81920 bytes

template<int KK, bool FC2>
__global__ __launch_bounds__(256)
void k_gemm(const float* __restrict__ Asrc,
            const float* __restrict__ Bsrc,    // [e][k][n], row stride UU
            const float* __restrict__ aux1,    // b1 / ctrl
            const float* __restrict__ aux2,    // -- / scaling
            float* __restrict__ out)
{
    extern __shared__ uint16_t pl[];
    __shared__ int   sRow[128];
    __shared__ float sBias[128];
    __shared__ float sCtrl[8][128];

    const int tid = threadIdx.x, wid = tid >> 5, lane = tid & 31;
    const int g = lane >> 2, tg = lane & 3;
    const int e = blockIdx.z;
    const int cnt = g_count[e];
    const int m0 = blockIdx.y * 128;
    if (m0 >= cnt) return;
    const int n0 = blockIdx.x * 128;
    const int base = g_off[e];

    if (tid < 128) {
        int m = m0 + tid;
        sRow[tid] = g_list[e * NT + (m < cnt ? m : cnt - 1)];
        sBias[tid] = FC2 ? aux2[e * UU + n0 + tid] : aux1[e * UU + n0 + tid];
    }
    if (FC2) {
        int b = tid >> 5, c = (tid & 31) * 4;
        *(float4*)&sCtrl[b][c] =
            *(const float4*)(aux1 + (size_t)e * 8 * UU + (size_t)b * UU + n0 + c);
    }
    __syncthreads();

    // ---- staging assignments ----
    // A: row = tid>>1 (0..127), k-half = (tid&1)*16; 16 values per chunk
    const int rowA = tid >> 1, k0A = (tid & 1) * 16;
    const float*    gAf = nullptr;
    const uint32_t* gAp = nullptr;
    if (FC2) {
        int mA = m0 + rowA; if (mA >= cnt) mA = cnt - 1;
        gAp = g_Hp + (size_t)(base + mA) * UU + k0A;
    } else {
        gAf = Asrc + (size_t)sRow[rowA] * DD + k0A;
    }
    uint16_t* dAh = pl + AH_OFF + rowA * PSTR + k0A;
    uint16_t* dAl = pl + AL_OFF + rowA * PSTR + k0A;
    // B: n = tid&127, k-half = (tid>>7)*16; 16 strided LDG.32 per chunk
    const int nB = tid & 127, k0B = (tid >> 7) * 16;
    const float* gB = Bsrc + (size_t)e * UU * KK + (size_t)k0B * UU + n0 + nB;
    uint16_t* dBh = pl + BH_OFF + nB * PSTR + k0B;
    uint16_t* dBl = pl + BL_OFF + nB * PSTR + k0B;

    const int m_base = (wid >> 2) * 64;
    const int n_base = (wid & 3) * 32;

    // ---- ldmatrix lane addresses (byte addrs into shared) ----
    const uint32_t plU = smem_to_u32(pl);
    const uint32_t aRow = (uint32_t)(m_base + (lane & 7) + ((lane >> 3) & 1) * 8);
    const uint32_t aCol = (uint32_t)(((lane >> 4) & 1) * 8);
    const uint32_t aH = plU + (AH_OFF + aRow * PSTR + aCol) * 2;
    const uint32_t aL = plU + (AL_OFF + aRow * PSTR + aCol) * 2;
    const uint32_t bRow = (uint32_t)(n_base + (lane & 7) + ((lane >> 4) & 1) * 8);
    const uint32_t bCol = (uint32_t)(((lane >> 3) & 1) * 8);
    const uint32_t bH = plU + (BH_OFF + bRow * PSTR + bCol) * 2;
    const uint32_t bL = plU + (BL_OFF + bRow * PSTR + bCol) * 2;

    float acc[4][4][4];
#pragma unroll
    for (int mi = 0; mi < 4; mi++)
#pragma unroll
        for (int ni = 0; ni < 4; ni++)
#pragma unroll
            for (int q = 0; q < 4; q++) acc[mi][ni][q] = 0.f;

    const int NCH = KK / BKC;
    float4 pA[4]; uint4 pW[4]; float pB[16];
    if (FC2) {
#pragma unroll
        for (int j = 0; j < 4; j++) pW[j] = ((const uint4*)gAp)[j];
    } else {
#pragma unroll
        for (int j = 0; j < 4; j++) pA[j] = *(const float4*)(gAf + 4 * j);
    }
#pragma unroll
    for (int j = 0; j < 16; j++) pB[j] = gB[(size_t)j * UU];

    for (int ch = 0; ch < NCH; ch++) {
        const uint32_t so = (uint32_t)(ch & 1) * STG_ELEM;
        const uint32_t so2 = so * 2;
        // convert + store current chunk
        if (FC2) {
            const uint32_t* w = (const uint32_t*)pW;
            uint4 h0, h1, l0, l1;
            h0.x = prmt(w[0],  w[1],  0x7632u); l0.x = prmt(w[0],  w[1],  0x5410u);
            h0.y = prmt(w[2],  w[3],  0x7632u); l0.y = prmt(w[2],  w[3],  0x5410u);
            h0.z = prmt(w[4],  w[5],  0x7632u); l0.z = prmt(w[4],  w[5],  0x5410u);
            h0.w = prmt(w[6],  w[7],  0x7632u); l0.w = prmt(w[6],  w[7],  0x5410u);
            h1.x = prmt(w[8],  w[9],  0x7632u); l1.x = prmt(w[8],  w[9],  0x5410u);
            h1.y = prmt(w[10], w[11], 0x7632u); l1.y = prmt(w[10], w[11], 0x5410u);
            h1.z = prmt(w[12], w[13], 0x7632u); l1.z = prmt(w[12], w[13], 0x5410u);
            h1.w = prmt(w[14], w[15], 0x7632u); l1.w = prmt(w[14], w[15], 0x5410u);
            *(uint4*)(dAh + so)     = h0;  *(uint4*)(dAh + so + 8) = h1;
            *(uint4*)(dAl + so)     = l0;  *(uint4*)(dAl + so + 8) = l1;
        } else {
#pragma unroll
            for (int j = 0; j < 4; j++)
                split_store(dAh + so + 4 * j, dAl + so + 4 * j, pA[j]);
        }
#pragma unroll
        for (int j = 0; j < 4; j++)
            split_store(dBh + so + 4 * j, dBl + so + 4 * j,
                        make_float4(pB[4 * j], pB[4 * j + 1], pB[4 * j + 2], pB[4 * j + 3]));
        // prefetch next chunk
        if (ch + 1 < NCH) {
            const int k0 = (ch + 1) * BKC;
            if (FC2) {
#pragma unroll
                for (int j = 0; j < 4; j++) pW[j] = ((const uint4*)(gAp + k0))[j];
            } else {
#pragma unroll
                for (int j = 0; j < 4; j++) pA[j] = *(const float4*)(gAf + k0 + 4 * j);
            }
            const float* gBn = gB + (size_t)k0 * UU;
#pragma unroll
            for (int j = 0; j < 16; j++) pB[j] = gBn[(size_t)j * UU];
        }
        __syncthreads();
#pragma unroll
        for (int ks = 0; ks < 2; ks++) {
            const uint32_t kso = so2 + (uint32_t)ks * 32;
            uint32_t bh0[4], bh1[4], bl0[4], bl1[4];
            LDSM4(bh0, bH + kso);
            LDSM4(bh1, bH + kso + 16 * PSTR * 2);
            LDSM4(bl0, bL + kso);
            LDSM4(bl1, bL + kso + 16 * PSTR * 2);
#pragma unroll
            for (int mi = 0; mi < 4; mi++) {
                const uint32_t moff = (uint32_t)mi * (16 * PSTR * 2);
                uint32_t ah[4], al[4];
                LDSM4(ah, aH + kso + moff);
                LDSM4(al, aL + kso + moff);
                mma16(acc[mi][0], ah, bh0);
                mma16(acc[mi][0], ah, bl0);
                mma16(acc[mi][0], al, bh0);
                mma16(acc[mi][1], ah, bh0 + 2);
                mma16(acc[mi][1], ah, bl0 + 2);
                mma16(acc[mi][1], al, bh0 + 2);
                mma16(acc[mi][2], ah, bh1);
                mma16(acc[mi][2], ah, bl1);
                mma16(acc[mi][2], al, bh1);
                mma16(acc[mi][3], ah, bh1 + 2);
                mma16(acc[mi][3], ah, bl1 + 2);
                mma16(acc[mi][3], al, bh1 + 2);
            }
        }
        __syncthreads();
    }

    // ---------------- epilogue ----------------
#pragma unroll
    for (int mi = 0; mi < 4; mi++) {
#pragma unroll
        for (int half = 0; half < 2; half++) {
            const int rloc = m_base + mi * 16 + g + half * 8;
            const int m = m0 + rloc;
            if (m >= cnt) continue;
#pragma unroll
            for (int ni = 0; ni < 4; ni++) {
                const int cl = n_base + ni * 8 + 2 * tg;
                float z0 = acc[mi][ni][half * 2 + 0];
                float z1 = acc[mi][ni][half * 2 + 1];
                if (!FC2) {
                    float t0 = z0 + sBias[cl], t1 = z1 + sBias[cl + 1];
                    float h0 = t0 * __fdividef(1.f, 1.f + __expf(-t0));
                    float h1 = t1 * __fdividef(1.f, 1.f + __expf(-t1));
                    uint32_t* dst = g_Hp + (size_t)(base + m) * UU + n0 + cl;
                    *(uint2*)dst = make_uint2(packsplit(h0), packsplit(h1));
                } else {
                    float* dst = out + (size_t)sRow[rloc] * UU + n0 + cl;
                    float2 v;
#pragma unroll
                    for (int q = 0; q < 2; q++) {
                        float z = q ? z1 : z0;
                        float xn = __fdividef(1.f, 1.f + __expf(-z));
                        float s = 1e-6f, num = 0.f;
#pragma unroll
                        for (int b = 0; b < 8; b++) {
                            float d = xn - (float)b * (1.0f / 7.0f);
                            float w = __expf(-32.f * d * d);
                            s += w;
                            num += w * sCtrl[b][cl + q];
                        }
                        float r = __fdividef(num, s) * sBias[cl + q];
                        if (q) v.y = r; else v.x = r;
                    }
                    *(float2*)dst = v;
                }
            }
        }
    }
}

// ---------------- launch ----------------
extern "C" void kernel_launch(void* const* d_in, const int* in_sizes, int n_in,
                              void* d_out, int out_size) {
    const float* x       = (const float*)d_in[0];
    const float* W1      = (const float*)d_in[1];
    const float* b1      = (const float*)d_in[2];
    const float* proj    = (const float*)d_in[3];
    const float* ctrl    = (const float*)d_in[4];
    const float* scaling = (const float*)d_in[5];
    const float* Wg      = (const float*)d_in[6];
    const float* bg      = (const float*)d_in[7];
    float* out = (float*)d_out;

    static int attr_done = 0;
    if (!attr_done) {
        cudaFuncSetAttribute(k_gemm<DD, false>,
                             cudaFuncAttributeMaxDynamicSharedMemorySize, SMEM_DYN);
        cudaFuncSetAttribute(k_gemm<UU, true>,
                             cudaFuncAttributeMaxDynamicSharedMemorySize, SMEM_DYN);
        attr_done = 1;
    }

    k_zero<<<1, 32>>>();
    k_gate<<<NT / 8, 256>>>(x, Wg, bg);
    k_offs<<<1, 1>>>();
    dim3 grid(UU / 128, NT / 128, EE);
    k_gemm<DD, false><<<grid, 256, SMEM_DYN>>>(x, W1, b1, nullptr, out);
    k_gemm<UU, true><<<grid, 256, SMEM_DYN>>>(nullptr, proj, ctrl, scaling, out);
}

// round 12
// speedup vs baseline: 2.2494x; 1.1185x over previous
#include <cuda_runtime.h>
#include <cstdint>

#define NT 8192
#define DD 1024
#define UU 512
#define EE 8

// ---------------- helpers ----------------
__device__ __forceinline__ uint32_t smem_to_u32(const void* p) {
    uint32_t a;
    asm("{ .reg .u64 t; cvta.to.shared.u64 t, %1; cvt.u32.u64 %0, t; }" : "=r"(a) : "l"(p));
    return a;
}
__device__ __forceinline__ uint32_t packbf(float lo, float hi) {
    uint32_t r;
    asm("cvt.rn.bf16x2.f32 %0, %1, %2;" : "=r"(r) : "f"(hi), "f"(lo));
    return r;
}
__device__ __forceinline__ uint32_t prmt(uint32_t a, uint32_t b, uint32_t s) {
    uint32_t d; asm("prmt.b32 %0,%1,%2,%3;" : "=r"(d) : "r"(a), "r"(b), "r"(s));
    return d;
}
__device__ __forceinline__ uint32_t packsplit(float v) {
    uint16_t h; asm("cvt.rn.bf16.f32 %0, %1;" : "=h"(h) : "f"(v));
    float hf = __uint_as_float(((uint32_t)h) << 16);
    uint16_t l; float r = v - hf;
    asm("cvt.rn.bf16.f32 %0, %1;" : "=h"(l) : "f"(r));
    return (((uint32_t)h) << 16) | (uint32_t)l;
}
__device__ __forceinline__ void mma16(float* c, const uint32_t* a, const uint32_t* b) {
    asm volatile(
        "mma.sync.aligned.m16n8k16.row.col.f32.bf16.bf16.f32 "
        "{%0,%1,%2,%3}, {%4,%5,%6,%7}, {%8,%9}, {%0,%1,%2,%3};"
        : "+f"(c[0]), "+f"(c[1]), "+f"(c[2]), "+f"(c[3])
        : "r"(a[0]), "r"(a[1]), "r"(a[2]), "r"(a[3]), "r"(b[0]), "r"(b[1]));
}
#define LDSM4(r, addr) \
    asm volatile("ldmatrix.sync.aligned.m8n8.x4.shared.b16 {%0,%1,%2,%3}, [%4];" \
        : "=r"((r)[0]), "=r"((r)[1]), "=r"((r)[2]), "=r"((r)[3]) : "r"(addr))

__device__ __forceinline__ void split_store(uint16_t* hp, uint16_t* lp, float4 v) {
    uint32_t h01 = packbf(v.x, v.y);
    uint32_t h23 = packbf(v.z, v.w);
    float r0 = v.x - __uint_as_float(h01 << 16);
    float r1 = v.y - __uint_as_float(h01 & 0xffff0000u);
    float r2 = v.z - __uint_as_float(h23 << 16);
    float r3 = v.w - __uint_as_float(h23 & 0xffff0000u);
    uint32_t l01 = packbf(r0, r1);
    uint32_t l23 = packbf(r2, r3);
    *(uint2*)hp = make_uint2(h01, h23);
    *(uint2*)lp = make_uint2(l01, l23);
}

// ---------------- scratch ----------------
__device__ int      g_count[EE];
__device__ int      g_off[EE];
__device__ int      g_list[EE * NT];
__device__ uint32_t g_Hp[NT * UU];     // packed (bf16 hi<<16 | bf16 lo)

// ---------------- small kernels ----------------
__global__ void k_zero() { if (threadIdx.x < EE) g_count[threadIdx.x] = 0; }

__global__ void k_gate(const float* __restrict__ x,
                       const float* __restrict__ Wg,
                       const float* __restrict__ bg) {
    int warp = (blockIdx.x * blockDim.x + threadIdx.x) >> 5;
    int lane = threadIdx.x & 31;
    if (warp >= NT) return;
    const float* xr = x + (size_t)warp * DD;
    float acc[EE];
#pragma unroll
    for (int e = 0; e < EE; e++) acc[e] = 0.f;
    for (int d = lane; d < DD; d += 32) {
        float xv = xr[d];
        const float4* wr = (const float4*)(Wg + d * EE);
        float4 w0 = wr[0], w1 = wr[1];
        acc[0] += xv * w0.x; acc[1] += xv * w0.y;
        acc[2] += xv * w0.z; acc[3] += xv * w0.w;
        acc[4] += xv * w1.x; acc[5] += xv * w1.y;
        acc[6] += xv * w1.z; acc[7] += xv * w1.w;
    }
#pragma unroll
    for (int e = 0; e < EE; e++)
#pragma unroll
        for (int off = 16; off; off >>= 1)
            acc[e] += __shfl_xor_sync(0xffffffffu, acc[e], off);
    if (lane == 0) {
        int best = 0; float bv = acc[0] + bg[0];
#pragma unroll
        for (int e = 1; e < EE; e++) {
            float v = acc[e] + bg[e];
            if (v > bv) { bv = v; best = e; }
        }
        int pos = atomicAdd(&g_count[best], 1);
        g_list[best * NT + pos] = warp;
    }
}

__global__ void k_offs() {
    if (threadIdx.x == 0) {
        int s = 0;
#pragma unroll
        for (int e = 0; e < EE; e++) { g_off[e] = s; s += g_count[e]; }
    }
}

// ---------------- bf16 m16n8k16 GEMM, 3xBF16 split, ldmatrix fragments ----------------
// CTA 256x128, 512 threads, 16 warps (4m x 4n), warp tile 64x32, BK=32.
// SMEM planes (bf16, row stride 40): Ah/Al [256][40], Bh/Bl [128][40] ([n][k]).
#define TM 256
#define BKC 32
#define PSTR 40
#define AH_OFF 0
#define AL_OFF (TM * PSTR)
#define BH_OFF (2 * TM * PSTR)
#define BL_OFF (2 * TM * PSTR + 128 * PSTR)
#define STG_ELEM (2 * TM * PSTR + 2 * 128 * PSTR)   // 30720 bf16
#define SMEM_DYN (2 * STG_ELEM * 2)                 // 122880 bytes

template<int KK, bool FC2>
__global__ __launch_bounds__(512)
void k_gemm(const float* __restrict__ Asrc,
            const float* __restrict__ Bsrc,    // [e][k][n], row stride UU
            const float* __restrict__ aux1,    // b1 / ctrl
            const float* __restrict__ aux2,    // -- / scaling
            float* __restrict__ out)
{
    extern __shared__ uint16_t pl[];
    __shared__ int   sRow[TM];
    __shared__ float sBias[128];
    __shared__ float sCtrl[8][128];

    const int tid = threadIdx.x, wid = tid >> 5, lane = tid & 31;
    const int g = lane >> 2, tg = lane & 3;
    const int e = blockIdx.z;
    const int cnt = g_count[e];
    const int m0 = blockIdx.y * TM;
    if (m0 >= cnt) return;
    const int n0 = blockIdx.x * 128;
    const int base = g_off[e];

    if (tid < TM) {
        int m = m0 + tid;
        sRow[tid] = g_list[e * NT + (m < cnt ? m : cnt - 1)];
    }
    if (tid < 128)
        sBias[tid] = FC2 ? aux2[e * UU + n0 + tid] : aux1[e * UU + n0 + tid];
    if (FC2 && tid < 256) {
        int b = tid >> 5, c = (tid & 31) * 4;
        *(float4*)&sCtrl[b][c] =
            *(const float4*)(aux1 + (size_t)e * 8 * UU + (size_t)b * UU + n0 + c);
    }
    __syncthreads();

    // ---- staging assignments ----
    // A: row = tid>>1 (0..255), k-half = (tid&1)*16; 16 values/chunk
    const int rowA = tid >> 1, k0A = (tid & 1) * 16;
    const float*    gAf = nullptr;
    const uint32_t* gAp = nullptr;
    if (FC2) {
        int mA = m0 + rowA; if (mA >= cnt) mA = cnt - 1;
        gAp = g_Hp + (size_t)(base + mA) * UU + k0A;
    } else {
        gAf = Asrc + (size_t)sRow[rowA] * DD + k0A;
    }
    uint16_t* dAh = pl + AH_OFF + rowA * PSTR + k0A;
    uint16_t* dAl = pl + AL_OFF + rowA * PSTR + k0A;
    // B: n = tid&127, k-quarter = (tid>>7)*8; 8 strided LDG.32 per chunk
    const int nB = tid & 127, k0B = (tid >> 7) * 8;
    const float* gB = Bsrc + (size_t)e * UU * KK + (size_t)k0B * UU + n0 + nB;
    uint16_t* dBh = pl + BH_OFF + nB * PSTR + k0B;
    uint16_t* dBl = pl + BL_OFF + nB * PSTR + k0B;

    const int m_base = (wid >> 2) * 64;
    const int n_base = (wid & 3) * 32;

    // ---- ldmatrix lane addresses ----
    const uint32_t plU = smem_to_u32(pl);
    const uint32_t aRow = (uint32_t)(m_base + (lane & 7) + ((lane >> 3) & 1) * 8);
    const uint32_t aCol = (uint32_t)(((lane >> 4) & 1) * 8);
    const uint32_t aH = plU + (AH_OFF + aRow * PSTR + aCol) * 2;
    const uint32_t aL = plU + (AL_OFF + aRow * PSTR + aCol) * 2;
    const uint32_t bRow = (uint32_t)(n_base + (lane & 7) + ((lane >> 4) & 1) * 8);
    const uint32_t bCol = (uint32_t)(((lane >> 3) & 1) * 8);
    const uint32_t bH = plU + (BH_OFF + bRow * PSTR + bCol) * 2;
    const uint32_t bL = plU + (BL_OFF + bRow * PSTR + bCol) * 2;

    float acc[4][4][4];
#pragma unroll
    for (int mi = 0; mi < 4; mi++)
#pragma unroll
        for (int ni = 0; ni < 4; ni++)
#pragma unroll
            for (int q = 0; q < 4; q++) acc[mi][ni][q] = 0.f;

    const int NCH = KK / BKC;
    float4 pA[4]; uint4 pW[4]; float pB[8];
    if (FC2) {
#pragma unroll
        for (int j = 0; j < 4; j++) pW[j] = ((const uint4*)gAp)[j];
    } else {
#pragma unroll
        for (int j = 0; j < 4; j++) pA[j] = *(const float4*)(gAf + 4 * j);
    }
#pragma unroll
    for (int j = 0; j < 8; j++) pB[j] = gB[(size_t)j * UU];

    for (int ch = 0; ch < NCH; ch++) {
        const uint32_t so = (uint32_t)(ch & 1) * STG_ELEM;
        const uint32_t so2 = so * 2;
        // convert + store current chunk
        if (FC2) {
            const uint32_t* w = (const uint32_t*)pW;
            uint4 h0, h1, l0, l1;
            h0.x = prmt(w[0],  w[1],  0x7632u); l0.x = prmt(w[0],  w[1],  0x5410u);
            h0.y = prmt(w[2],  w[3],  0x7632u); l0.y = prmt(w[2],  w[3],  0x5410u);
            h0.z = prmt(w[4],  w[5],  0x7632u); l0.z = prmt(w[4],  w[5],  0x5410u);
            h0.w = prmt(w[6],  w[7],  0x7632u); l0.w = prmt(w[6],  w[7],  0x5410u);
            h1.x = prmt(w[8],  w[9],  0x7632u); l1.x = prmt(w[8],  w[9],  0x5410u);
            h1.y = prmt(w[10], w[11], 0x7632u); l1.y = prmt(w[10], w[11], 0x5410u);
            h1.z = prmt(w[12], w[13], 0x7632u); l1.z = prmt(w[12], w[13], 0x5410u);
            h1.w = prmt(w[14], w[15], 0x7632u); l1.w = prmt(w[14], w[15], 0x5410u);
            *(uint4*)(dAh + so)     = h0;  *(uint4*)(dAh + so + 8) = h1;
            *(uint4*)(dAl + so)     = l0;  *(uint4*)(dAl + so + 8) = l1;
        } else {
#pragma unroll
            for (int j = 0; j < 4; j++)
                split_store(dAh + so + 4 * j, dAl + so + 4 * j, pA[j]);
        }
        split_store(dBh + so,     dBl + so,     make_float4(pB[0], pB[1], pB[2], pB[3]));
        split_store(dBh + so + 4, dBl + so + 4, make_float4(pB[4], pB[5], pB[6], pB[7]));
        // prefetch next chunk
        if (ch + 1 < NCH) {
            const int k0 = (ch + 1) * BKC;
            if (FC2) {
#pragma unroll
                for (int j = 0; j < 4; j++) pW[j] = ((const uint4*)(gAp + k0))[j];
            } else {
#pragma unroll
                for (int j = 0; j < 4; j++) pA[j] = *(const float4*)(gAf + k0 + 4 * j);
            }
            const float* gBn = gB + (size_t)k0 * UU;
#pragma unroll
            for (int j = 0; j < 8; j++) pB[j] = gBn[(size_t)j * UU];
        }
        __syncthreads();
#pragma unroll
        for (int ks = 0; ks < 2; ks++) {
            const uint32_t kso = so2 + (uint32_t)ks * 32;
            uint32_t bh0[4], bh1[4], bl0[4], bl1[4];
            LDSM4(bh0, bH + kso);
            LDSM4(bh1, bH + kso + 16 * PSTR * 2);
            LDSM4(bl0, bL + kso);
            LDSM4(bl1, bL + kso + 16 * PSTR * 2);
#pragma unroll
            for (int mi = 0; mi < 4; mi++) {
                const uint32_t moff = (uint32_t)mi * (16 * PSTR * 2);
                uint32_t ah[4], al[4];
                LDSM4(ah, aH + kso + moff);
                LDSM4(al, aL + kso + moff);
                mma16(acc[mi][0], ah, bh0);
                mma16(acc[mi][0], ah, bl0);
                mma16(acc[mi][0], al, bh0);
                mma16(acc[mi][1], ah, bh0 + 2);
                mma16(acc[mi][1], ah, bl0 + 2);
                mma16(acc[mi][1], al, bh0 + 2);
                mma16(acc[mi][2], ah, bh1);
                mma16(acc[mi][2], ah, bl1);
                mma16(acc[mi][2], al, bh1);
                mma16(acc[mi][3], ah, bh1 + 2);
                mma16(acc[mi][3], ah, bl1 + 2);
                mma16(acc[mi][3], al, bh1 + 2);
            }
        }
        __syncthreads();
    }

    // ---------------- epilogue ----------------
#pragma unroll
    for (int mi = 0; mi < 4; mi++) {
#pragma unroll
        for (int half = 0; half < 2; half++) {
            const int rloc = m_base + mi * 16 + g + half * 8;
            const int m = m0 + rloc;
            if (m >= cnt) continue;
#pragma unroll
            for (int ni = 0; ni < 4; ni++) {
                const int cl = n_base + ni * 8 + 2 * tg;
                float z0 = acc[mi][ni][half * 2 + 0];
                float z1 = acc[mi][ni][half * 2 + 1];
                if (!FC2) {
                    float t0 = z0 + sBias[cl], t1 = z1 + sBias[cl + 1];
                    float h0 = t0 * __fdividef(1.f, 1.f + __expf(-t0));
                    float h1 = t1 * __fdividef(1.f, 1.f + __expf(-t1));
                    uint32_t* dst = g_Hp + (size_t)(base + m) * UU + n0 + cl;
                    *(uint2*)dst = make_uint2(packsplit(h0), packsplit(h1));
                } else {
                    float* dst = out + (size_t)sRow[rloc] * UU + n0 + cl;
                    float2 v;
#pragma unroll
                    for (int q = 0; q < 2; q++) {
                        float z = q ? z1 : z0;
                        float xn = __fdividef(1.f, 1.f + __expf(-z));
                        float s = 1e-6f, num = 0.f;
#pragma unroll
                        for (int b = 0; b < 8; b++) {
                            float d = xn - (float)b * (1.0f / 7.0f);
                            float w = __expf(-32.f * d * d);
                            s += w;
                            num += w * sCtrl[b][cl + q];
                        }
                        float r = __fdividef(num, s) * sBias[cl + q];
                        if (q) v.y = r; else v.x = r;
                    }
                    *(float2*)dst = v;
                }
            }
        }
    }
}

// ---------------- launch ----------------
extern "C" void kernel_launch(void* const* d_in, const int* in_sizes, int n_in,
                              void* d_out, int out_size) {
    const float* x       = (const float*)d_in[0];
    const float* W1      = (const float*)d_in[1];
    const float* b1      = (const float*)d_in[2];
    const float* proj    = (const float*)d_in[3];
    const float* ctrl    = (const float*)d_in[4];
    const float* scaling = (const float*)d_in[5];
    const float* Wg      = (const float*)d_in[6];
    const float* bg      = (const float*)d_in[7];
    float* out = (float*)d_out;

    static int attr_done = 0;
    if (!attr_done) {
        cudaFuncSetAttribute(k_gemm<DD, false>,
                             cudaFuncAttributeMaxDynamicSharedMemorySize, SMEM_DYN);
        cudaFuncSetAttribute(k_gemm<UU, true>,
                             cudaFuncAttributeMaxDynamicSharedMemorySize, SMEM_DYN);
        attr_done = 1;
    }

    k_zero<<<1, 32>>>();
    k_gate<<<NT / 8, 256>>>(x, Wg, bg);
    k_offs<<<1, 1>>>();
    dim3 grid(UU / 128, NT / TM, EE);
    k_gemm<DD, false><<<grid, 512, SMEM_DYN>>>(x, W1, b1, nullptr, out);
    k_gemm<UU, true><<<grid, 512, SMEM_DYN>>>(nullptr, proj, ctrl, scaling, out);
}

// round 13
// speedup vs baseline: 2.3443x; 1.0422x over previous
#include <cuda_runtime.h>
#include <cstdint>

#define NT 8192
#define DD 1024
#define UU 512
#define EE 8

// ---------------- helpers ----------------
__device__ __forceinline__ uint32_t smem_to_u32(const void* p) {
    uint32_t a;
    asm("{ .reg .u64 t; cvta.to.shared.u64 t, %1; cvt.u32.u64 %0, t; }" : "=r"(a) : "l"(p));
    return a;
}
__device__ __forceinline__ uint32_t packbf(float lo, float hi) {
    uint32_t r;
    asm("cvt.rn.bf16x2.f32 %0, %1, %2;" : "=r"(r) : "f"(hi), "f"(lo));
    return r;
}
__device__ __forceinline__ uint32_t prmt(uint32_t a, uint32_t b, uint32_t s) {
    uint32_t d; asm("prmt.b32 %0,%1,%2,%3;" : "=r"(d) : "r"(a), "r"(b), "r"(s));
    return d;
}
__device__ __forceinline__ uint32_t packsplit(float v) {
    uint16_t h; asm("cvt.rn.bf16.f32 %0, %1;" : "=h"(h) : "f"(v));
    float hf = __uint_as_float(((uint32_t)h) << 16);
    uint16_t l; float r = v - hf;
    asm("cvt.rn.bf16.f32 %0, %1;" : "=h"(l) : "f"(r));
    return (((uint32_t)h) << 16) | (uint32_t)l;
}
__device__ __forceinline__ void mma16(float* c, const uint32_t* a, const uint32_t* b) {
    asm volatile(
        "mma.sync.aligned.m16n8k16.row.col.f32.bf16.bf16.f32 "
        "{%0,%1,%2,%3}, {%4,%5,%6,%7}, {%8,%9}, {%0,%1,%2,%3};"
        : "+f"(c[0]), "+f"(c[1]), "+f"(c[2]), "+f"(c[3])
        : "r"(a[0]), "r"(a[1]), "r"(a[2]), "r"(a[3]), "r"(b[0]), "r"(b[1]));
}
#define LDSM4(r, addr) \
    asm volatile("ldmatrix.sync.aligned.m8n8.x4.shared.b16 {%0,%1,%2,%3}, [%4];" \
        : "=r"((r)[0]), "=r"((r)[1]), "=r"((r)[2]), "=r"((r)[3]) : "r"(addr))

__device__ __forceinline__ void split_store(uint16_t* hp, uint16_t* lp, float4 v) {
    uint32_t h01 = packbf(v.x, v.y);
    uint32_t h23 = packbf(v.z, v.w);
    float r0 = v.x - __uint_as_float(h01 << 16);
    float r1 = v.y - __uint_as_float(h01 & 0xffff0000u);
    float r2 = v.z - __uint_as_float(h23 << 16);
    float r3 = v.w - __uint_as_float(h23 & 0xffff0000u);
    uint32_t l01 = packbf(r0, r1);
    uint32_t l23 = packbf(r2, r3);
    *(uint2*)hp = make_uint2(h01, h23);
    *(uint2*)lp = make_uint2(l01, l23);
}

// ---------------- scratch ----------------
__device__ int      g_count[EE];
__device__ int      g_off[EE];
__device__ int      g_list[EE * NT];
__device__ uint32_t g_Hp[NT * UU];     // packed (bf16 hi<<16 | bf16 lo)

// ---------------- small kernels ----------------
__global__ void k_zero() { if (threadIdx.x < EE) g_count[threadIdx.x] = 0; }

__global__ void k_gate(const float* __restrict__ x,
                       const float* __restrict__ Wg,
                       const float* __restrict__ bg) {
    int warp = (blockIdx.x * blockDim.x + threadIdx.x) >> 5;
    int lane = threadIdx.x & 31;
    if (warp >= NT) return;
    const float* xr = x + (size_t)warp * DD;
    float acc[EE];
#pragma unroll
    for (int e = 0; e < EE; e++) acc[e] = 0.f;
    for (int d = lane; d < DD; d += 32) {
        float xv = xr[d];
        const float4* wr = (const float4*)(Wg + d * EE);
        float4 w0 = wr[0], w1 = wr[1];
        acc[0] += xv * w0.x; acc[1] += xv * w0.y;
        acc[2] += xv * w0.z; acc[3] += xv * w0.w;
        acc[4] += xv * w1.x; acc[5] += xv * w1.y;
        acc[6] += xv * w1.z; acc[7] += xv * w1.w;
    }
#pragma unroll
    for (int e = 0; e < EE; e++)
#pragma unroll
        for (int off = 16; off; off >>= 1)
            acc[e] += __shfl_xor_sync(0xffffffffu, acc[e], off);
    if (lane == 0) {
        int best = 0; float bv = acc[0] + bg[0];
#pragma unroll
        for (int e = 1; e < EE; e++) {
            float v = acc[e] + bg[e];
            if (v > bv) { bv = v; best = e; }
        }
        int pos = atomicAdd(&g_count[best], 1);
        g_list[best * NT + pos] = warp;
    }
}

__global__ void k_offs() {
    if (threadIdx.x == 0) {
        int s = 0;
#pragma unroll
        for (int e = 0; e < EE; e++) { g_off[e] = s; s += g_count[e]; }
    }
}

// ---------------- bf16 m16n8k16 GEMM, 3xBF16 split, single-barrier pipeline ----------------
// CTA 256x128, 512 threads, 16 warps (4m x 4n), warp tile 64x32, BK=32.
// SMEM planes (bf16, row stride 40): Ah/Al [256][40], Bh/Bl [128][40] ([n][k]).
// One __syncthreads per chunk: iteration ch MMAs stage ch&1 while storing
// stage (ch+1)&1 -- disjoint stages, hazards ordered by the single barrier.
#define TM 256
#define BKC 32
#define PSTR 40
#define AH_OFF 0
#define AL_OFF (TM * PSTR)
#define BH_OFF (2 * TM * PSTR)
#define BL_OFF (2 * TM * PSTR + 128 * PSTR)
#define STG_ELEM (2 * TM * PSTR + 2 * 128 * PSTR)   // 30720 bf16
#define SMEM_DYN (2 * STG_ELEM * 2)                 // 122880 bytes

template<int KK, bool FC2>
__global__ __launch_bounds__(512)
void k_gemm(const float* __restrict__ Asrc,
            const float* __restrict__ Bsrc,    // [e][k][n], row stride UU
            const float* __restrict__ aux1,    // b1 / ctrl
            const float* __restrict__ aux2,    // -- / scaling
            float* __restrict__ out)
{
    extern __shared__ uint16_t pl[];
    __shared__ int   sRow[TM];
    __shared__ float sBias[128];
    __shared__ float sCtrl[8][128];

    const int tid = threadIdx.x, wid = tid >> 5, lane = tid & 31;
    const int g = lane >> 2, tg = lane & 3;
    const int e = blockIdx.z;
    const int cnt = g_count[e];
    const int m0 = blockIdx.y * TM;
    if (m0 >= cnt) return;
    const int n0 = blockIdx.x * 128;
    const int base = g_off[e];

    if (tid < TM) {
        int m = m0 + tid;
        sRow[tid] = g_list[e * NT + (m < cnt ? m : cnt - 1)];
    }
    if (tid < 128)
        sBias[tid] = FC2 ? aux2[e * UU + n0 + tid] : aux1[e * UU + n0 + tid];
    if (FC2 && tid < 256) {
        int b = tid >> 5, c = (tid & 31) * 4;
        *(float4*)&sCtrl[b][c] =
            *(const float4*)(aux1 + (size_t)e * 8 * UU + (size_t)b * UU + n0 + c);
    }
    __syncthreads();

    // ---- staging assignments ----
    const int rowA = tid >> 1, k0A = (tid & 1) * 16;
    const float*    gAf = nullptr;
    const uint32_t* gAp = nullptr;
    if (FC2) {
        int mA = m0 + rowA; if (mA >= cnt) mA = cnt - 1;
        gAp = g_Hp + (size_t)(base + mA) * UU + k0A;
    } else {
        gAf = Asrc + (size_t)sRow[rowA] * DD + k0A;
    }
    uint16_t* dAh = pl + AH_OFF + rowA * PSTR + k0A;
    uint16_t* dAl = pl + AL_OFF + rowA * PSTR + k0A;
    const int nB = tid & 127, k0B = (tid >> 7) * 8;
    const float* gB = Bsrc + (size_t)e * UU * KK + (size_t)k0B * UU + n0 + nB;
    uint16_t* dBh = pl + BH_OFF + nB * PSTR + k0B;
    uint16_t* dBl = pl + BL_OFF + nB * PSTR + k0B;

    const int m_base = (wid >> 2) * 64;
    const int n_base = (wid & 3) * 32;

    // ---- ldmatrix lane addresses ----
    const uint32_t plU = smem_to_u32(pl);
    const uint32_t aRow = (uint32_t)(m_base + (lane & 7) + ((lane >> 3) & 1) * 8);
    const uint32_t aCol = (uint32_t)(((lane >> 4) & 1) * 8);
    const uint32_t aH = plU + (AH_OFF + aRow * PSTR + aCol) * 2;
    const uint32_t aL = plU + (AL_OFF + aRow * PSTR + aCol) * 2;
    const uint32_t bRow = (uint32_t)(n_base + (lane & 7) + ((lane >> 4) & 1) * 8);
    const uint32_t bCol = (uint32_t)(((lane >> 3) & 1) * 8);
    const uint32_t bH = plU + (BH_OFF + bRow * PSTR + bCol) * 2;
    const uint32_t bL = plU + (BL_OFF + bRow * PSTR + bCol) * 2;

    float acc[4][4][4];
#pragma unroll
    for (int mi = 0; mi < 4; mi++)
#pragma unroll
        for (int ni = 0; ni < 4; ni++)
#pragma unroll
            for (int q = 0; q < 4; q++) acc[mi][ni][q] = 0.f;

    float4 pA[4]; uint4 pW[4]; float pB[8];

    auto prefetch = [&](int ch) {
        const int k0 = ch * BKC;
        if (FC2) {
#pragma unroll
            for (int j = 0; j < 4; j++) pW[j] = ((const uint4*)(gAp + k0))[j];
        } else {
#pragma unroll
            for (int j = 0; j < 4; j++) pA[j] = *(const float4*)(gAf + k0 + 4 * j);
        }
        const float* gBn = gB + (size_t)k0 * UU;
#pragma unroll
        for (int j = 0; j < 8; j++) pB[j] = gBn[(size_t)j * UU];
    };
    auto store_stage = [&](int stg) {
        const uint32_t so = (uint32_t)stg * STG_ELEM;
        if (FC2) {
            const uint32_t* w = (const uint32_t*)pW;
            uint4 h0, h1, l0, l1;
            h0.x = prmt(w[0],  w[1],  0x7632u); l0.x = prmt(w[0],  w[1],  0x5410u);
            h0.y = prmt(w[2],  w[3],  0x7632u); l0.y = prmt(w[2],  w[3],  0x5410u);
            h0.z = prmt(w[4],  w[5],  0x7632u); l0.z = prmt(w[4],  w[5],  0x5410u);
            h0.w = prmt(w[6],  w[7],  0x7632u); l0.w = prmt(w[6],  w[7],  0x5410u);
            h1.x = prmt(w[8],  w[9],  0x7632u); l1.x = prmt(w[8],  w[9],  0x5410u);
            h1.y = prmt(w[10], w[11], 0x7632u); l1.y = prmt(w[10], w[11], 0x5410u);
            h1.z = prmt(w[12], w[13], 0x7632u); l1.z = prmt(w[12], w[13], 0x5410u);
            h1.w = prmt(w[14], w[15], 0x7632u); l1.w = prmt(w[14], w[15], 0x5410u);
            *(uint4*)(dAh + so)     = h0;  *(uint4*)(dAh + so + 8) = h1;
            *(uint4*)(dAl + so)     = l0;  *(uint4*)(dAl + so + 8) = l1;
        } else {
#pragma unroll
            for (int j = 0; j < 4; j++)
                split_store(dAh + so + 4 * j, dAl + so + 4 * j, pA[j]);
        }
        split_store(dBh + so,     dBl + so,     make_float4(pB[0], pB[1], pB[2], pB[3]));
        split_store(dBh + so + 4, dBl + so + 4, make_float4(pB[4], pB[5], pB[6], pB[7]));
    };

    const int NCH = KK / BKC;
    prefetch(0);
    store_stage(0);

    for (int ch = 0; ch < NCH; ch++) {
        __syncthreads();
        if (ch + 1 < NCH) prefetch(ch + 1);     // LDG latency covered by MMAs below
        const uint32_t so2 = (uint32_t)(ch & 1) * (STG_ELEM * 2);
#pragma unroll
        for (int ks = 0; ks < 2; ks++) {
            const uint32_t kso = so2 + (uint32_t)ks * 32;
            uint32_t bh0[4], bh1[4], bl0[4], bl1[4];
            LDSM4(bh0, bH + kso);
            LDSM4(bh1, bH + kso + 16 * PSTR * 2);
            LDSM4(bl0, bL + kso);
            LDSM4(bl1, bL + kso + 16 * PSTR * 2);
#pragma unroll
            for (int mi = 0; mi < 4; mi++) {
                const uint32_t moff = (uint32_t)mi * (16 * PSTR * 2);
                uint32_t ah[4], al[4];
                LDSM4(ah, aH + kso + moff);
                LDSM4(al, aL + kso + moff);
                mma16(acc[mi][0], ah, bh0);
                mma16(acc[mi][0], ah, bl0);
                mma16(acc[mi][0], al, bh0);
                mma16(acc[mi][1], ah, bh0 + 2);
                mma16(acc[mi][1], ah, bl0 + 2);
                mma16(acc[mi][1], al, bh0 + 2);
                mma16(acc[mi][2], ah, bh1);
                mma16(acc[mi][2], ah, bl1);
                mma16(acc[mi][2], al, bh1);
                mma16(acc[mi][3], ah, bh1 + 2);
                mma16(acc[mi][3], ah, bl1 + 2);
                mma16(acc[mi][3], al, bh1 + 2);
            }
        }
        if (ch + 1 < NCH) store_stage((ch + 1) & 1);   // overlaps tensor-pipe drain
    }

    // ---------------- epilogue ----------------
#pragma unroll
    for (int mi = 0; mi < 4; mi++) {
#pragma unroll
        for (int half = 0; half < 2; half++) {
            const int rloc = m_base + mi * 16 + g + half * 8;
            const int m = m0 + rloc;
            if (m >= cnt) continue;
#pragma unroll
            for (int ni = 0; ni < 4; ni++) {
                const int cl = n_base + ni * 8 + 2 * tg;
                float z0 = acc[mi][ni][half * 2 + 0];
                float z1 = acc[mi][ni][half * 2 + 1];
                if (!FC2) {
                    float t0 = z0 + sBias[cl], t1 = z1 + sBias[cl + 1];
                    float h0 = t0 * __fdividef(1.f, 1.f + __expf(-t0));
                    float h1 = t1 * __fdividef(1.f, 1.f + __expf(-t1));
                    uint32_t* dst = g_Hp + (size_t)(base + m) * UU + n0 + cl;
                    *(uint2*)dst = make_uint2(packsplit(h0), packsplit(h1));
                } else {
                    float* dst = out + (size_t)sRow[rloc] * UU + n0 + cl;
                    float2 v;
#pragma unroll
                    for (int q = 0; q < 2; q++) {
                        float z = q ? z1 : z0;
                        float xn = __fdividef(1.f, 1.f + __expf(-z));
                        float s = 1e-6f, num = 0.f;
#pragma unroll
                        for (int b = 0; b < 8; b++) {
                            float d = xn - (float)b * (1.0f / 7.0f);
                            float w = __expf(-32.f * d * d);
                            s += w;
                            num += w * sCtrl[b][cl + q];
                        }
                        float r = __fdividef(num, s) * sBias[cl + q];
                        if (q) v.y = r; else v.x = r;
                    }
                    *(float2*)dst = v;
                }
            }
        }
    }
}

// ---------------- launch ----------------
extern "C" void kernel_launch(void* const* d_in, const int* in_sizes, int n_in,
                              void* d_out, int out_size) {
    const float* x       = (const float*)d_in[0];
    const float* W1      = (const float*)d_in[1];
    const float* b1      = (const float*)d_in[2];
    const float* proj    = (const float*)d_in[3];
    const float* ctrl    = (const float*)d_in[4];
    const float* scaling = (const float*)d_in[5];
    const float* Wg      = (const float*)d_in[6];
    const float* bg      = (const float*)d_in[7];
    float* out = (float*)d_out;

    static int attr_done = 0;
    if (!attr_done) {
        cudaFuncSetAttribute(k_gemm<DD, false>,
                             cudaFuncAttributeMaxDynamicSharedMemorySize, SMEM_DYN);
        cudaFuncSetAttribute(k_gemm<UU, true>,
                             cudaFuncAttributeMaxDynamicSharedMemorySize, SMEM_DYN);
        attr_done = 1;
    }

    k_zero<<<1, 32>>>();
    k_gate<<<NT / 8, 256>>>(x, Wg, bg);
    k_offs<<<1, 1>>>();
    dim3 grid(UU / 128, NT / TM, EE);
    k_gemm<DD, false><<<grid, 512, SMEM_DYN>>>(x, W1, b1, nullptr, out);
    k_gemm<UU, true><<<grid, 512, SMEM_DYN>>>(nullptr, proj, ctrl, scaling, out);
}

// round 15
// speedup vs baseline: 2.8264x; 1.2057x over previous
#include <cuda_runtime.h>
#include <cuda_fp16.h>
#include <cstdint>

#define NT 8192
#define DD 1024
#define UU 512
#define EE 8

// ---------------- helpers ----------------
__device__ __forceinline__ uint32_t smem_to_u32(const void* p) {
    uint32_t a;
    asm("{ .reg .u64 t; cvta.to.shared.u64 t, %1; cvt.u32.u64 %0, t; }" : "=r"(a) : "l"(p));
    return a;
}
__device__ __forceinline__ uint32_t prmt(uint32_t a, uint32_t b, uint32_t s) {
    uint32_t d; asm("prmt.b32 %0,%1,%2,%3;" : "=r"(d) : "r"(a), "r"(b), "r"(s));
    return d;
}
__device__ __forceinline__ uint32_t h2u(__half2 h) { return *(uint32_t*)&h; }

// pack float -> (f16(v) << 16) | f16(v - f16(v))
__device__ __forceinline__ uint32_t packsplit16(float v) {
    __half h = __float2half_rn(v);
    float hf = __half2float(h);
    __half l = __float2half_rn(v - hf);
    return (((uint32_t)__half_as_ushort(h)) << 16) | (uint32_t)__half_as_ushort(l);
}
__device__ __forceinline__ void mma16(float* c, const uint32_t* a, const uint32_t* b) {
    asm volatile(
        "mma.sync.aligned.m16n8k16.row.col.f32.f16.f16.f32 "
        "{%0,%1,%2,%3}, {%4,%5,%6,%7}, {%8,%9}, {%0,%1,%2,%3};"
        : "+f"(c[0]), "+f"(c[1]), "+f"(c[2]), "+f"(c[3])
        : "r"(a[0]), "r"(a[1]), "r"(a[2]), "r"(a[3]), "r"(b[0]), "r"(b[1]));
}
#define LDSM4(r, addr) \
    asm volatile("ldmatrix.sync.aligned.m8n8.x4.shared.b16 {%0,%1,%2,%3}, [%4];" \
        : "=r"((r)[0]), "=r"((r)[1]), "=r"((r)[2]), "=r"((r)[3]) : "r"(addr))

// split float4 -> f16 hi plane + f16 residual plane (8B each)
__device__ __forceinline__ void split_store4_f16(uint16_t* hp, uint16_t* lp, float4 v) {
    __half2 h01 = __floats2half2_rn(v.x, v.y);   // .x -> lo half
    __half2 h23 = __floats2half2_rn(v.z, v.w);
    float2 f01 = __half22float2(h01);
    float2 f23 = __half22float2(h23);
    __half2 l01 = __floats2half2_rn(v.x - f01.x, v.y - f01.y);
    __half2 l23 = __floats2half2_rn(v.z - f23.x, v.w - f23.y);
    *(uint2*)hp = make_uint2(h2u(h01), h2u(h23));
    *(uint2*)lp = make_uint2(h2u(l01), h2u(l23));
}

// ---------------- scratch ----------------
__device__ int      g_count[EE];
__device__ int      g_off[EE];
__device__ int      g_list[EE * NT];
__device__ uint32_t g_Hp[NT * UU];     // packed (f16 hi<<16 | f16 lo)

// ---------------- small kernels ----------------
__global__ void k_zero() { if (threadIdx.x < EE) g_count[threadIdx.x] = 0; }

__global__ void k_gate(const float* __restrict__ x,
                       const float* __restrict__ Wg,
                       const float* __restrict__ bg) {
    int warp = (blockIdx.x * blockDim.x + threadIdx.x) >> 5;
    int lane = threadIdx.x & 31;
    if (warp >= NT) return;
    const float* xr = x + (size_t)warp * DD;
    float acc[EE];
#pragma unroll
    for (int e = 0; e < EE; e++) acc[e] = 0.f;
    for (int d = lane; d < DD; d += 32) {
        float xv = xr[d];
        const float4* wr = (const float4*)(Wg + d * EE);
        float4 w0 = wr[0], w1 = wr[1];
        acc[0] += xv * w0.x; acc[1] += xv * w0.y;
        acc[2] += xv * w0.z; acc[3] += xv * w0.w;
        acc[4] += xv * w1.x; acc[5] += xv * w1.y;
        acc[6] += xv * w1.z; acc[7] += xv * w1.w;
    }
#pragma unroll
    for (int e = 0; e < EE; e++)
#pragma unroll
        for (int off = 16; off; off >>= 1)
            acc[e] += __shfl_xor_sync(0xffffffffu, acc[e], off);
    if (lane == 0) {
        int best = 0; float bv = acc[0] + bg[0];
#pragma unroll
        for (int e = 1; e < EE; e++) {
            float v = acc[e] + bg[e];
            if (v > bv) { bv = v; best = e; }
        }
        int pos = atomicAdd(&g_count[best], 1);
        g_list[best * NT + pos] = warp;
    }
}

__global__ void k_offs() {
    if (threadIdx.x == 0) {
        int s = 0;
#pragma unroll
        for (int e = 0; e < EE; e++) { g_off[e] = s; s += g_count[e]; }
    }
}

// ---------------- fp16 m16n8k16 GEMM, A hi/lo split + single-plane B ----------------
// CTA 256x128, 512 threads, 16 warps (4m x 4n), warp tile 64x32, BK=32.
// SMEM planes (f16, row stride 40): Ah/Al [256][40], Bh [128][40] ([n][k]).
// Single __syncthreads per chunk (2-stage pipeline, store next while MMA current).
#define TM 256
#define BKC 32
#define PSTR 40
#define AH_OFF 0
#define AL_OFF (TM * PSTR)
#define BH_OFF (2 * TM * PSTR)
#define STG_ELEM (2 * TM * PSTR + 128 * PSTR)   // 25600 f16
#define SMEM_DYN (2 * STG_ELEM * 2)             // 102400 bytes

template<int KK, bool FC2>
__global__ __launch_bounds__(512)
void k_gemm(const float* __restrict__ Asrc,
            const float* __restrict__ Bsrc,    // [e][k][n], row stride UU
            const float* __restrict__ aux1,    // b1 / ctrl
            const float* __restrict__ aux2,    // -- / scaling
            float* __restrict__ out)
{
    extern __shared__ uint16_t pl[];
    __shared__ int   sRow[TM];
    __shared__ float sBias[128];
    __shared__ float sCtrl[8][128];

    const int tid = threadIdx.x, wid = tid >> 5, lane = tid & 31;
    const int g = lane >> 2, tg = lane & 3;
    const int e = blockIdx.z;
    const int cnt = g_count[e];
    const int m0 = blockIdx.y * TM;
    if (m0 >= cnt) return;
    const int n0 = blockIdx.x * 128;
    const int base = g_off[e];

    if (tid < TM) {
        int m = m0 + tid;
        sRow[tid] = g_list[e * NT + (m < cnt ? m : cnt - 1)];
    }
    if (tid < 128)
        sBias[tid] = FC2 ? aux2[e * UU + n0 + tid] : aux1[e * UU + n0 + tid];
    if (FC2 && tid < 256) {
        int b = tid >> 5, c = (tid & 31) * 4;
        *(float4*)&sCtrl[b][c] =
            *(const float4*)(aux1 + (size_t)e * 8 * UU + (size_t)b * UU + n0 + c);
    }
    __syncthreads();

    // ---- staging assignments ----
    const int rowA = tid >> 1, k0A = (tid & 1) * 16;
    const float*    gAf = nullptr;
    const uint32_t* gAp = nullptr;
    if (FC2) {
        int mA = m0 + rowA; if (mA >= cnt) mA = cnt - 1;
        gAp = g_Hp + (size_t)(base + mA) * UU + k0A;
    } else {
        gAf = Asrc + (size_t)sRow[rowA] * DD + k0A;
    }
    uint16_t* dAh = pl + AH_OFF + rowA * PSTR + k0A;
    uint16_t* dAl = pl + AL_OFF + rowA * PSTR + k0A;
    const int nB = tid & 127, k0B = (tid >> 7) * 8;
    const float* gB = Bsrc + (size_t)e * UU * KK + (size_t)k0B * UU + n0 + nB;
    uint16_t* dBh = pl + BH_OFF + nB * PSTR + k0B;

    const int m_base = (wid >> 2) * 64;
    const int n_base = (wid & 3) * 32;

    // ---- ldmatrix lane addresses ----
    const uint32_t plU = smem_to_u32(pl);
    const uint32_t aRow = (uint32_t)(m_base + (lane & 7) + ((lane >> 3) & 1) * 8);
    const uint32_t aCol = (uint32_t)(((lane >> 4) & 1) * 8);
    const uint32_t aH = plU + (AH_OFF + aRow * PSTR + aCol) * 2;
    const uint32_t aL = plU + (AL_OFF + aRow * PSTR + aCol) * 2;
    const uint32_t bRow = (uint32_t)(n_base + (lane & 7) + ((lane >> 4) & 1) * 8);
    const uint32_t bCol = (uint32_t)(((lane >> 3) & 1) * 8);
    const uint32_t bH = plU + (BH_OFF + bRow * PSTR + bCol) * 2;

    float acc[4][4][4];
#pragma unroll
    for (int mi = 0; mi < 4; mi++)
#pragma unroll
        for (int ni = 0; ni < 4; ni++)
#pragma unroll
            for (int q = 0; q < 4; q++) acc[mi][ni][q] = 0.f;

    float4 pA[4]; uint4 pW[4]; float pB[8];

    auto prefetch = [&](int ch) {
        const int k0 = ch * BKC;
        if (FC2) {
#pragma unroll
            for (int j = 0; j < 4; j++) pW[j] = ((const uint4*)(gAp + k0))[j];
        } else {
#pragma unroll
            for (int j = 0; j < 4; j++) pA[j] = *(const float4*)(gAf + k0 + 4 * j);
        }
        const float* gBn = gB + (size_t)k0 * UU;
#pragma unroll
        for (int j = 0; j < 8; j++) pB[j] = gBn[(size_t)j * UU];
    };
    auto store_stage = [&](int stg) {
        const uint32_t so = (uint32_t)stg * STG_ELEM;
        if (FC2) {
            const uint32_t* w = (const uint32_t*)pW;
            uint4 h0, h1, l0, l1;
            h0.x = prmt(w[0],  w[1],  0x7632u); l0.x = prmt(w[0],  w[1],  0x5410u);
            h0.y = prmt(w[2],  w[3],  0x7632u); l0.y = prmt(w[2],  w[3],  0x5410u);
            h0.z = prmt(w[4],  w[5],  0x7632u); l0.z = prmt(w[4],  w[5],  0x5410u);
            h0.w = prmt(w[6],  w[7],  0x7632u); l0.w = prmt(w[6],  w[7],  0x5410u);
            h1.x = prmt(w[8],  w[9],  0x7632u); l1.x = prmt(w[8],  w[9],  0x5410u);
            h1.y = prmt(w[10], w[11], 0x7632u); l1.y = prmt(w[10], w[11], 0x5410u);
            h1.z = prmt(w[12], w[13], 0x7632u); l1.z = prmt(w[12], w[13], 0x5410u);
            h1.w = prmt(w[14], w[15], 0x7632u); l1.w = prmt(w[14], w[15], 0x5410u);
            *(uint4*)(dAh + so)     = h0;  *(uint4*)(dAh + so + 8) = h1;
            *(uint4*)(dAl + so)     = l0;  *(uint4*)(dAl + so + 8) = l1;
        } else {
#pragma unroll
            for (int j = 0; j < 4; j++)
                split_store4_f16(dAh + so + 4 * j, dAl + so + 4 * j, pA[j]);
        }
        // B: single f16 hi plane, 8 values = one uint4
        __half2 b01 = __floats2half2_rn(pB[0], pB[1]);
        __half2 b23 = __floats2half2_rn(pB[2], pB[3]);
        __half2 b45 = __floats2half2_rn(pB[4], pB[5]);
        __half2 b67 = __floats2half2_rn(pB[6], pB[7]);
        *(uint4*)(dBh + so) = make_uint4(h2u(b01), h2u(b23), h2u(b45), h2u(b67));
    };

    const int NCH = KK / BKC;
    prefetch(0);
    store_stage(0);

    for (int ch = 0; ch < NCH; ch++) {
        __syncthreads();
        if (ch + 1 < NCH) prefetch(ch + 1);
        const uint32_t so2 = (uint32_t)(ch & 1) * (STG_ELEM * 2);
#pragma unroll
        for (int ks = 0; ks < 2; ks++) {
            const uint32_t kso = so2 + (uint32_t)ks * 32;
            uint32_t bh0[4], bh1[4];
            LDSM4(bh0, bH + kso);
            LDSM4(bh1, bH + kso + 16 * PSTR * 2);
#pragma unroll
            for (int mi = 0; mi < 4; mi++) {
                const uint32_t moff = (uint32_t)mi * (16 * PSTR * 2);
                uint32_t ah[4], al[4];
                LDSM4(ah, aH + kso + moff);
                LDSM4(al, aL + kso + moff);
                mma16(acc[mi][0], ah, bh0);
                mma16(acc[mi][0], al, bh0);
                mma16(acc[mi][1], ah, bh0 + 2);
                mma16(acc[mi][1], al, bh0 + 2);
                mma16(acc[mi][2], ah, bh1);
                mma16(acc[mi][2], al, bh1);
                mma16(acc[mi][3], ah, bh1 + 2);
                mma16(acc[mi][3], al, bh1 + 2);
            }
        }
        if (ch + 1 < NCH) store_stage((ch + 1) & 1);
    }

    // ---------------- epilogue ----------------
    // RBF factorization: w_b = exp(-32(xn-b/7)^2) = C * t^b * E_b,
    // C = exp(-32 xn^2), t = exp((64/7) xn), E_b = exp(-32 b^2/49).
    const float Eb[8] = {1.0f, 0.5204501f, 0.07336967f, 0.0028016589f,
                         2.897785e-5f, 8.118545e-8f, 6.160956e-11f, 1.2664166e-14f};
#pragma unroll
    for (int mi = 0; mi < 4; mi++) {
#pragma unroll
        for (int half = 0; half < 2; half++) {
            const int rloc = m_base + mi * 16 + g + half * 8;
            const int m = m0 + rloc;
            if (m >= cnt) continue;
#pragma unroll
            for (int ni = 0; ni < 4; ni++) {
                const int cl = n_base + ni * 8 + 2 * tg;
                float z0 = acc[mi][ni][half * 2 + 0];
                float z1 = acc[mi][ni][half * 2 + 1];
                if (!FC2) {
                    float t0 = z0 + sBias[cl], t1 = z1 + sBias[cl + 1];
                    float h0 = t0 * __fdividef(1.f, 1.f + __expf(-t0));
                    float h1 = t1 * __fdividef(1.f, 1.f + __expf(-t1));
                    uint32_t* dst = g_Hp + (size_t)(base + m) * UU + n0 + cl;
                    *(uint2*)dst = make_uint2(packsplit16(h0), packsplit16(h1));
                } else {
                    float* dst = out + (size_t)sRow[rloc] * UU + n0 + cl;
                    float2 v;
#pragma unroll
                    for (int q = 0; q < 2; q++) {
                        float z = q ? z1 : z0;
                        float xn = __fdividef(1.f, 1.f + __expf(-z));
                        float C = __expf(-32.f * xn * xn);
                        float t = __expf((64.f / 7.f) * xn);
                        float tb = C;
                        float s = 1e-6f, num = 0.f;
#pragma unroll
                        for (int b = 0; b < 8; b++) {
                            float w = tb * Eb[b];
                            s += w;
                            num += w * sCtrl[b][cl + q];
                            tb *= t;
                        }
                        float r = __fdividef(num, s) * sBias[cl + q];
                        if (q) v.y = r; else v.x = r;
                    }
                    *(float2*)dst = v;
                }
            }
        }
    }
}

// ---------------- launch ----------------
extern "C" void kernel_launch(void* const* d_in, const int* in_sizes, int n_in,
                              void* d_out, int out_size) {
    const float* x       = (const float*)d_in[0];
    const float* W1      = (const float*)d_in[1];
    const float* b1      = (const float*)d_in[2];
    const float* proj    = (const float*)d_in[3];
    const float* ctrl    = (const float*)d_in[4];
    const float* scaling = (const float*)d_in[5];
    const float* Wg      = (const float*)d_in[6];
    const float* bg      = (const float*)d_in[7];
    float* out = (float*)d_out;

    static int attr_done = 0;
    if (!attr_done) {
        cudaFuncSetAttribute(k_gemm<DD, false>,
                             cudaFuncAttributeMaxDynamicSharedMemorySize, SMEM_DYN);
        cudaFuncSetAttribute(k_gemm<UU, true>,
                             cudaFuncAttributeMaxDynamicSharedMemorySize, SMEM_DYN);
        attr_done = 1;
    }

    k_zero<<<1, 32>>>();
    k_gate<<<NT / 8, 256>>>(x, Wg, bg);
    k_offs<<<1, 1>>>();
    dim3 grid(UU / 128, NT / TM, EE);
    k_gemm<DD, false><<<grid, 512, SMEM_DYN>>>(x, W1, b1, nullptr, out);
    k_gemm<UU, true><<<grid, 512, SMEM_DYN>>>(nullptr, proj, ctrl, scaling, out);
}